// round 5
// baseline (speedup 1.0000x reference)
#include <cuda_runtime.h>
#include <math.h>
#include <cstdint>

// Problem constants
#define BDIM 4096
#define HDIM 1024
#define SDIM 256
#define NSAMP 256
#define TSTEPS 10
#define RHDIM 512
#define N3 3072

#define BN 32
#define BK 32
#define BROW 40              // B smem row stride (pad 32->40), conflict-free

// k1 tiling: BM=256, 8 warps x (32 rows x 32 cols)
#define BM1 256
#define ASTG1 8192           // 256*32 words per A stage
#define ABASE1 24576         // 3 * ASTG1
// k2/k3 tiling: BM=128, 8 warps x (16 rows x 32 cols)
#define BM 128
#define ASTG 4096
#define ABASE 12288

// Persistent scratch
__device__ float g_h[2][BDIM * HDIM];
__device__ float g_s[BDIM * SDIM];
__device__ float g_relu[BDIM * RHDIM];
__device__ float g_acc[BDIM];
// Pre-permuted tf32 weights (fragment-ready layout)
__device__ float W1p[32 * 40 * 3 * 1024];   // [cb][kt][g][k][32]
__device__ float W2p[8 * 32 * 2 * 1024];    // [cb][kt][g][k][32]
__device__ float W3p[16 * 40 * 1024];       // [cb][kt][k][32]

__device__ __forceinline__ float sigm_(float x) { return 1.0f / (1.0f + expf(-x)); }
__device__ __forceinline__ float softplus_(float x) {
    return fmaxf(x, 0.0f) + log1pf(expf(-fabsf(x)));
}
__device__ __forceinline__ float f2tf(float x) {
    unsigned u; asm("cvt.rna.tf32.f32 %0, %1;" : "=r"(u) : "f"(x));
    return __uint_as_float(u);
}
__device__ __forceinline__ void mma_tf32(float c[4], float a0, float a1, float a2, float a3,
                                         float b0, float b1) {
    asm volatile(
        "mma.sync.aligned.m16n8k8.row.col.f32.tf32.tf32.f32 "
        "{%0,%1,%2,%3},{%4,%5,%6,%7},{%8,%9},{%0,%1,%2,%3};\n"
        : "+f"(c[0]), "+f"(c[1]), "+f"(c[2]), "+f"(c[3])
        : "r"(__float_as_uint(a0)), "r"(__float_as_uint(a1)),
          "r"(__float_as_uint(a2)), "r"(__float_as_uint(a3)),
          "r"(__float_as_uint(b0)), "r"(__float_as_uint(b1)));
}
__device__ __forceinline__ void cp16(uint32_t dst, const float* src) {
    asm volatile("cp.async.cg.shared.global [%0], [%1], 16;" :: "r"(dst), "l"(src));
}
__device__ __forceinline__ void cp_commit() { asm volatile("cp.async.commit_group;"); }
template<int N> __device__ __forceinline__ void cp_wait() {
    asm volatile("cp.async.wait_group %0;" :: "n"(N));
}

// ---------------------------------------------------------------------------
// init + weight permutation
// ---------------------------------------------------------------------------
__global__ void k_init(const float* __restrict__ h0, const float* __restrict__ s0) {
    int idx = blockIdx.x * blockDim.x + threadIdx.x;
    int stride = gridDim.x * blockDim.x;
    for (int i = idx; i < BDIM * HDIM; i += stride) g_h[0][i] = h0[i & (HDIM - 1)];
    for (int i = idx; i < BDIM * SDIM; i += stride) g_s[i] = s0[i & (SDIM - 1)];
    for (int i = idx; i < BDIM; i += stride) g_acc[i] = 0.0f;
}

// dst[cb][kt][g][k][p], p = c8*4+nt where src col = nt*8+c8
__global__ void k_prep1(const float* __restrict__ Wx, const float* __restrict__ Wh) {
    const int total = 32 * 40 * 3 * 1024;
    for (int idx = blockIdx.x * blockDim.x + threadIdx.x; idx < total;
         idx += gridDim.x * blockDim.x) {
        int p = idx & 31, k = (idx >> 5) & 31;
        int rest = idx >> 10;
        int g = rest % 3; rest /= 3;
        int kt = rest % 40; int cb = rest / 40;
        int c = (p & 3) * 8 + (p >> 2);
        int row = kt * 32 + k;
        float v = (row < 256) ? Wx[(size_t)row * N3 + g * HDIM + cb * 32 + c]
                              : Wh[(size_t)(row - 256) * N3 + g * HDIM + cb * 32 + c];
        W1p[idx] = f2tf(v);
    }
}
__global__ void k_prep2(const float* __restrict__ W_mu, const float* __restrict__ W_std) {
    const int total = 8 * 32 * 2 * 1024;
    for (int idx = blockIdx.x * blockDim.x + threadIdx.x; idx < total;
         idx += gridDim.x * blockDim.x) {
        int p = idx & 31, k = (idx >> 5) & 31;
        int rest = idx >> 10;
        int g = rest & 1; rest >>= 1;
        int kt = rest & 31; int cb = rest >> 5;
        int c = (p & 3) * 8 + (p >> 2);
        const float* W = g ? W_std : W_mu;
        W2p[idx] = f2tf(W[(size_t)(kt * 32 + k) * SDIM + cb * 32 + c]);
    }
}
__global__ void k_prep3(const float* __restrict__ W_r1) {
    const int total = 16 * 40 * 1024;
    for (int idx = blockIdx.x * blockDim.x + threadIdx.x; idx < total;
         idx += gridDim.x * blockDim.x) {
        int p = idx & 31, k = (idx >> 5) & 31;
        int rest = idx >> 10;
        int kt = rest % 40; int cb = rest / 40;
        int c = (p & 3) * 8 + (p >> 2);
        W3p[idx] = f2tf(W_r1[(size_t)(kt * 32 + k) * RHDIM + cb * 32 + c]);
    }
}

// ---------------------------------------------------------------------------
// K1: GRU gates GEMM, cp.async 3-stage pipeline, tf32 mma.
// BM=256, 8 warps each 32 rows x 32 cols (two m16 tiles). grid (16,32).
// ---------------------------------------------------------------------------
__global__ __launch_bounds__(256, 1)
void k1_gru(int par, const float* __restrict__ Wx,
            const float* __restrict__ b_gru, const int* __restrict__ acts_t) {
    extern __shared__ float smem[];
    const float* __restrict__ h_in = g_h[par];
    float* __restrict__ h_out = g_h[par ^ 1];

    const int tid = threadIdx.x, lane = tid & 31, warp = tid >> 5;
    const int row0 = blockIdx.x * BM1, col0 = blockIdx.y * BN;
    const int wr = warp * 32;
    const uint32_t smem_b = (uint32_t)__cvta_generic_to_shared(smem);

    // cp.async A: 8 chunks/thread. r = rbase + 32i, c4 = tid&7
    const int c4 = tid & 7, rbase = tid >> 3, rx0 = rbase & 7;
    int dstAw[8];
#pragma unroll
    for (int i = 0; i < 8; i++) dstAw[i] = (rbase + 32 * i) * 32 + (c4 ^ rx0) * 4;
    const float* sA = g_s + (size_t)(row0 + rbase) * SDIM + c4 * 4;
    const float* hA = h_in + (size_t)(row0 + rbase) * HDIM + c4 * 4;
    // cp.async B: 3 chunks/thread (one per gate)
    const int bk = tid >> 3;  // 0..31
    const int dstBw = bk * BROW + c4 * 4;
    const float* wblk = W1p + (size_t)blockIdx.y * (40 * 3 * 1024) + bk * 32 + c4 * 4;

#define K1_ISSUE(kt, s) do {                                                  \
    const float* ap; int astr;                                                \
    if ((kt) < 8) { ap = sA + (kt) * 32; astr = SDIM; }                       \
    else { ap = hA + ((kt) - 8) * 32; astr = HDIM; }                          \
    _Pragma("unroll")                                                         \
    for (int i = 0; i < 8; i++)                                               \
        cp16(smem_b + 4 * ((s) * ASTG1 + dstAw[i]), ap + (size_t)(32 * i) * astr); \
    const float* wp = wblk + (size_t)(kt) * 3072;                             \
    _Pragma("unroll")                                                         \
    for (int g = 0; g < 3; g++)                                               \
        cp16(smem_b + 4 * (ABASE1 + (s) * 3840 + dstBw + g * 1280), wp + g * 1024); \
    cp_commit(); } while (0)

    float acc[3][2][4][4];   // [gate][mt][ntile][reg]
    float accNX[2][4][4];
#pragma unroll
    for (int g = 0; g < 3; g++)
#pragma unroll
        for (int mt = 0; mt < 2; mt++)
#pragma unroll
            for (int nt = 0; nt < 4; nt++)
#pragma unroll
                for (int r = 0; r < 4; r++) acc[g][mt][nt][r] = 0.0f;

    const int q = lane >> 2, klo = lane & 3;
    const int r1 = wr + q;                 // mt=0 base row; mt=1 adds 16
    const int rx = r1 & 7;                 // same low-3 bits for +8/+16/+24
    const int bfr = klo * BROW + q * 4;    // B fragment base (within gate)

    K1_ISSUE(0, 0);
    K1_ISSUE(1, 1);

    const int KT = 40;
#pragma unroll 1
    for (int kt = 0; kt < KT; ++kt) {
        if (kt + 1 < KT) cp_wait<1>(); else cp_wait<0>();
        __syncthreads();
        if (kt + 2 < KT) K1_ISSUE(kt + 2, (kt + 2) % 3);

        if (kt == 8) {
#pragma unroll
            for (int mt = 0; mt < 2; mt++)
#pragma unroll
                for (int nt = 0; nt < 4; nt++)
#pragma unroll
                    for (int r = 0; r < 4; r++) {
                        accNX[mt][nt][r] = acc[2][mt][nt][r];
                        acc[2][mt][nt][r] = 0.0f;
                    }
        }
        const int sA_ = (kt % 3) * ASTG1;
        const int sB_ = ABASE1 + (kt % 3) * 3840;
#pragma unroll
        for (int kc = 0; kc < 4; ++kc) {
            const int kA = klo + ((2 * kc) ^ rx) * 4;
            const int kB = klo + ((2 * kc + 1) ^ rx) * 4;
            float a[2][4];
#pragma unroll
            for (int mt = 0; mt < 2; mt++) {
                const int rw = (r1 + mt * 16) * 32;
                a[mt][0] = smem[sA_ + rw + kA];
                a[mt][1] = smem[sA_ + rw + 8 * 32 + kA];
                a[mt][2] = smem[sA_ + rw + kB];
                a[mt][3] = smem[sA_ + rw + 8 * 32 + kB];
            }
#pragma unroll
            for (int g = 0; g < 3; g++) {
                const int bb = sB_ + g * 1280 + kc * 8 * BROW + bfr;
                float4 b0 = *(const float4*)&smem[bb];
                float4 b1 = *(const float4*)&smem[bb + 4 * BROW];
#pragma unroll
                for (int mt = 0; mt < 2; mt++) {
                    mma_tf32(acc[g][mt][0], a[mt][0], a[mt][1], a[mt][2], a[mt][3], b0.x, b1.x);
                    mma_tf32(acc[g][mt][1], a[mt][0], a[mt][1], a[mt][2], a[mt][3], b0.y, b1.y);
                    mma_tf32(acc[g][mt][2], a[mt][0], a[mt][1], a[mt][2], a[mt][3], b0.z, b1.z);
                    mma_tf32(acc[g][mt][3], a[mt][0], a[mt][1], a[mt][2], a[mt][3], b0.w, b1.w);
                }
            }
        }
    }
#undef K1_ISSUE

#pragma unroll
    for (int mt = 0; mt < 2; mt++) {
#pragma unroll
        for (int ri = 0; ri < 2; ri++) {
            int b = row0 + r1 + mt * 16 + ri * 8;
            int a = acts_t[b];
            const float* wa = Wx + (size_t)(SDIM + a) * N3;
#pragma unroll
            for (int nt = 0; nt < 4; nt++) {
#pragma unroll
                for (int cj = 0; cj < 2; cj++) {
                    int c = col0 + nt * 8 + 2 * klo + cj;
                    int idx = ri * 2 + cj;
                    float z = sigm_(acc[0][mt][nt][idx] + wa[c] + b_gru[c]);
                    float r = sigm_(acc[1][mt][nt][idx] + wa[HDIM + c] + b_gru[HDIM + c]);
                    float n = tanhf(accNX[mt][nt][idx] + wa[2 * HDIM + c]
                                    + r * acc[2][mt][nt][idx] + b_gru[2 * HDIM + c]);
                    float hp = h_in[(size_t)b * HDIM + c];
                    h_out[(size_t)b * HDIM + c] = (1.0f - z) * hp + z * n;
                }
            }
        }
    }
}

// ---------------------------------------------------------------------------
// K2: mu/std GEMM + latent sample. grid (32,8). (unchanged from R4)
// ---------------------------------------------------------------------------
__global__ __launch_bounds__(256, 2)
void k2_latent(int parn, const float* __restrict__ b_mu, const float* __restrict__ b_std,
               const float* __restrict__ noise_t) {
    extern __shared__ float smem[];
    const float* __restrict__ h_new = g_h[parn];

    const int tid = threadIdx.x, lane = tid & 31, warp = tid >> 5;
    const int row0 = blockIdx.x * BM, col0 = blockIdx.y * BN;
    const int wr = warp * 16;
    const uint32_t smem_b = (uint32_t)__cvta_generic_to_shared(smem);

    const int c4 = tid & 7, rbase = tid >> 3, rx0 = rbase & 7;
    int dstAw[4];
#pragma unroll
    for (int i = 0; i < 4; i++) dstAw[i] = (rbase + 32 * i) * 32 + (c4 ^ rx0) * 4;
    const float* hA = h_new + (size_t)(row0 + rbase) * HDIM + c4 * 4;
    const int bk = tid >> 3;
    const int dstBw = bk * BROW + c4 * 4;
    const float* wblk = W2p + (size_t)blockIdx.y * (32 * 2 * 1024) + bk * 32 + c4 * 4;

#define K2_ISSUE(kt, s) do {                                                  \
    const float* ap = hA + (kt) * 32;                                         \
    _Pragma("unroll")                                                         \
    for (int i = 0; i < 4; i++)                                               \
        cp16(smem_b + 4 * ((s) * ASTG + dstAw[i]), ap + (size_t)(32 * i) * HDIM); \
    const float* wp = wblk + (size_t)(kt) * 2048;                             \
    _Pragma("unroll")                                                         \
    for (int g = 0; g < 2; g++)                                               \
        cp16(smem_b + 4 * (3 * ASTG + (s) * 2560 + dstBw + g * 1280), wp + g * 1024); \
    cp_commit(); } while (0)

    float acc[2][4][4];
#pragma unroll
    for (int g = 0; g < 2; g++)
#pragma unroll
        for (int nt = 0; nt < 4; nt++)
#pragma unroll
            for (int r = 0; r < 4; r++) acc[g][nt][r] = 0.0f;

    const int q = lane >> 2, klo = lane & 3;
    const int r1 = wr + q;
    const int rx = r1 & 7;
    const int r1w = r1 * 32 + klo, r2w = (r1 + 8) * 32 + klo;
    const int bfr = klo * BROW + q * 4;

    K2_ISSUE(0, 0);
    K2_ISSUE(1, 1);

    const int KT = 32;
#pragma unroll 1
    for (int kt = 0; kt < KT; ++kt) {
        if (kt + 1 < KT) cp_wait<1>(); else cp_wait<0>();
        __syncthreads();
        if (kt + 2 < KT) K2_ISSUE(kt + 2, (kt + 2) % 3);

        const int sA_ = (kt % 3) * ASTG;
        const int sB_ = ABASE + (kt % 3) * 2560;
#pragma unroll
        for (int kc = 0; kc < 4; ++kc) {
            float a0 = smem[sA_ + r1w + ((2 * kc) ^ rx) * 4];
            float a1 = smem[sA_ + r2w + ((2 * kc) ^ rx) * 4];
            float a2 = smem[sA_ + r1w + ((2 * kc + 1) ^ rx) * 4];
            float a3 = smem[sA_ + r2w + ((2 * kc + 1) ^ rx) * 4];
#pragma unroll
            for (int g = 0; g < 2; g++) {
                const int bb = sB_ + g * 1280 + kc * 8 * BROW + bfr;
                float4 b0 = *(const float4*)&smem[bb];
                float4 b1 = *(const float4*)&smem[bb + 4 * BROW];
                mma_tf32(acc[g][0], a0, a1, a2, a3, b0.x, b1.x);
                mma_tf32(acc[g][1], a0, a1, a2, a3, b0.y, b1.y);
                mma_tf32(acc[g][2], a0, a1, a2, a3, b0.z, b1.z);
                mma_tf32(acc[g][3], a0, a1, a2, a3, b0.w, b1.w);
            }
        }
    }
#undef K2_ISSUE

#pragma unroll
    for (int ri = 0; ri < 2; ri++) {
        int b = row0 + r1 + ri * 8;
#pragma unroll
        for (int nt = 0; nt < 4; nt++) {
#pragma unroll
            for (int cj = 0; cj < 2; cj++) {
                int c = col0 + nt * 8 + 2 * klo + cj;
                int idx = ri * 2 + cj;
                float mu = acc[0][nt][idx] + b_mu[c];
                float sd = softplus_(acc[1][nt][idx] + b_std[c]) + 0.1f;
                g_s[(size_t)b * SDIM + c] = mu + sd * noise_t[(size_t)b * SDIM + c];
            }
        }
    }
}

// ---------------------------------------------------------------------------
// K3: reward hidden GEMM + ReLU. grid (32,16). (unchanged from R4)
// ---------------------------------------------------------------------------
__global__ __launch_bounds__(256, 2)
void k3_reward(int parn, const float* __restrict__ b_r1) {
    extern __shared__ float smem[];
    const float* __restrict__ h_new = g_h[parn];

    const int tid = threadIdx.x, lane = tid & 31, warp = tid >> 5;
    const int row0 = blockIdx.x * BM, col0 = blockIdx.y * BN;
    const int wr = warp * 16;
    const uint32_t smem_b = (uint32_t)__cvta_generic_to_shared(smem);

    const int c4 = tid & 7, rbase = tid >> 3, rx0 = rbase & 7;
    int dstAw[4];
#pragma unroll
    for (int i = 0; i < 4; i++) dstAw[i] = (rbase + 32 * i) * 32 + (c4 ^ rx0) * 4;
    const float* hA = h_new + (size_t)(row0 + rbase) * HDIM + c4 * 4;
    const float* sA = g_s + (size_t)(row0 + rbase) * SDIM + c4 * 4;
    const int bk = tid >> 3;
    const int dstBw = bk * BROW + c4 * 4;
    const float* wblk = W3p + (size_t)blockIdx.y * (40 * 1024) + bk * 32 + c4 * 4;

#define K3_ISSUE(kt, s) do {                                                  \
    const float* ap; int astr;                                                \
    if ((kt) < 32) { ap = hA + (kt) * 32; astr = HDIM; }                      \
    else { ap = sA + ((kt) - 32) * 32; astr = SDIM; }                         \
    _Pragma("unroll")                                                         \
    for (int i = 0; i < 4; i++)                                               \
        cp16(smem_b + 4 * ((s) * ASTG + dstAw[i]), ap + (size_t)(32 * i) * astr); \
    cp16(smem_b + 4 * (3 * ASTG + (s) * 1280 + dstBw), wblk + (size_t)(kt) * 1024); \
    cp_commit(); } while (0)

    float acc[4][4];
#pragma unroll
    for (int nt = 0; nt < 4; nt++)
#pragma unroll
        for (int r = 0; r < 4; r++) acc[nt][r] = 0.0f;

    const int q = lane >> 2, klo = lane & 3;
    const int r1 = wr + q;
    const int rx = r1 & 7;
    const int r1w = r1 * 32 + klo, r2w = (r1 + 8) * 32 + klo;
    const int bfr = klo * BROW + q * 4;

    K3_ISSUE(0, 0);
    K3_ISSUE(1, 1);

    const int KT = 40;
#pragma unroll 1
    for (int kt = 0; kt < KT; ++kt) {
        if (kt + 1 < KT) cp_wait<1>(); else cp_wait<0>();
        __syncthreads();
        if (kt + 2 < KT) K3_ISSUE(kt + 2, (kt + 2) % 3);

        const int sA_ = (kt % 3) * ASTG;
        const int sB_ = ABASE + (kt % 3) * 1280;
#pragma unroll
        for (int kc = 0; kc < 4; ++kc) {
            float a0 = smem[sA_ + r1w + ((2 * kc) ^ rx) * 4];
            float a1 = smem[sA_ + r2w + ((2 * kc) ^ rx) * 4];
            float a2 = smem[sA_ + r1w + ((2 * kc + 1) ^ rx) * 4];
            float a3 = smem[sA_ + r2w + ((2 * kc + 1) ^ rx) * 4];
            const int bb = sB_ + kc * 8 * BROW + bfr;
            float4 b0 = *(const float4*)&smem[bb];
            float4 b1 = *(const float4*)&smem[bb + 4 * BROW];
            mma_tf32(acc[0], a0, a1, a2, a3, b0.x, b1.x);
            mma_tf32(acc[1], a0, a1, a2, a3, b0.y, b1.y);
            mma_tf32(acc[2], a0, a1, a2, a3, b0.z, b1.z);
            mma_tf32(acc[3], a0, a1, a2, a3, b0.w, b1.w);
        }
    }
#undef K3_ISSUE

#pragma unroll
    for (int ri = 0; ri < 2; ri++) {
        int b = row0 + r1 + ri * 8;
#pragma unroll
        for (int nt = 0; nt < 4; nt++) {
#pragma unroll
            for (int cj = 0; cj < 2; cj++) {
                int c = col0 + nt * 8 + 2 * klo + cj;
                int idx = ri * 2 + cj;
                g_relu[(size_t)b * RHDIM + c] = fmaxf(acc[nt][idx] + b_r1[c], 0.0f);
            }
        }
    }
}

// ---------------------------------------------------------------------------
// K4 + final reductions (unchanged)
// ---------------------------------------------------------------------------
__global__ void k4_reduce(int parn, const float* __restrict__ w_r2,
                          const float* __restrict__ b_r2, float disc) {
    const int b = blockIdx.x;
    const int tid = threadIdx.x;
    const float* __restrict__ hr = g_h[parn] + (size_t)b * HDIM;
    const float* __restrict__ sr = g_s + (size_t)b * SDIM;
    const float* __restrict__ rr = g_relu + (size_t)b * RHDIM;

    float sum = 0.0f, sq = 0.0f, dot = 0.0f;
    for (int k = tid; k < HDIM; k += 128) { float v = hr[k]; sum += v; sq = fmaf(v, v, sq); }
    for (int k = tid; k < SDIM; k += 128) { float v = sr[k]; sum += v; sq = fmaf(v, v, sq); }
    for (int k = tid; k < RHDIM; k += 128) dot = fmaf(rr[k], w_r2[k], dot);

#pragma unroll
    for (int off = 16; off > 0; off >>= 1) {
        sum += __shfl_down_sync(0xffffffffu, sum, off);
        sq  += __shfl_down_sync(0xffffffffu, sq, off);
        dot += __shfl_down_sync(0xffffffffu, dot, off);
    }
    __shared__ float s1[4], s2[4], s3[4];
    if ((tid & 31) == 0) { s1[tid >> 5] = sum; s2[tid >> 5] = sq; s3[tid >> 5] = dot; }
    __syncthreads();
    if (tid == 0) {
        float S = s1[0] + s1[1] + s1[2] + s1[3];
        float Q = s2[0] + s2[1] + s2[2] + s2[3];
        float D = s3[0] + s3[1] + s3[2] + s3[3];
        float mean = S * (1.0f / 1280.0f);
        float var = Q * (1.0f / 1280.0f) - mean * mean;
        g_acc[b] += disc * ((D + b_r2[0]) + var);
    }
}

__global__ void k_final(float* __restrict__ out) {
    const int a = blockIdx.x;
    const int tid = threadIdx.x;
    float v = g_acc[a * NSAMP + tid];
#pragma unroll
    for (int off = 16; off > 0; off >>= 1) v += __shfl_down_sync(0xffffffffu, v, off);
    __shared__ float w[8];
    if ((tid & 31) == 0) w[tid >> 5] = v;
    __syncthreads();
    if (tid < 8) {
        float x = w[tid];
#pragma unroll
        for (int off = 4; off > 0; off >>= 1) x += __shfl_down_sync(0xffu, x, off);
        if (tid == 0) out[a] = -x * (1.0f / (float)NSAMP);
    }
}

// ---------------------------------------------------------------------------
extern "C" void kernel_launch(void* const* d_in, const int* in_sizes, int n_in,
                              void* d_out, int out_size) {
    (void)in_sizes; (void)n_in; (void)out_size;
    const float* h0    = (const float*)d_in[0];
    const float* s0    = (const float*)d_in[1];
    const float* noise = (const float*)d_in[2];
    const float* Wx    = (const float*)d_in[3];
    const float* Wh    = (const float*)d_in[4];
    const float* b_gru = (const float*)d_in[5];
    const float* W_mu  = (const float*)d_in[6];
    const float* b_mu  = (const float*)d_in[7];
    const float* W_std = (const float*)d_in[8];
    const float* b_std = (const float*)d_in[9];
    const float* W_r1  = (const float*)d_in[10];
    const float* b_r1  = (const float*)d_in[11];
    const float* w_r2  = (const float*)d_in[12];
    const float* b_r2  = (const float*)d_in[13];
    const int*   acts  = (const int*)d_in[14];
    float* out = (float*)d_out;

    const int SM1 = (ABASE1 + 3 * 3840) * 4;  // 144384 B
    const int SM2 = (ABASE + 3 * 2560) * 4;   // 79872 B
    const int SM3 = (ABASE + 3 * 1280) * 4;   // 64512 B
    cudaFuncSetAttribute(k1_gru, cudaFuncAttributeMaxDynamicSharedMemorySize, SM1);
    cudaFuncSetAttribute(k2_latent, cudaFuncAttributeMaxDynamicSharedMemorySize, SM2);
    cudaFuncSetAttribute(k3_reward, cudaFuncAttributeMaxDynamicSharedMemorySize, SM3);

    k_init<<<512, 256>>>(h0, s0);
    k_prep1<<<2048, 256>>>(Wx, Wh);
    k_prep2<<<512, 256>>>(W_mu, W_std);
    k_prep3<<<512, 256>>>(W_r1);

    float disc = 1.0f;
    for (int t = 0; t < TSTEPS; ++t) {
        int par = t & 1;
        int parn = par ^ 1;
        k1_gru<<<dim3(BDIM / BM1, HDIM / BN), 256, SM1>>>(par, Wx, b_gru, acts + (size_t)t * BDIM);
        k2_latent<<<dim3(BDIM / BM, SDIM / BN), 256, SM2>>>(parn, b_mu, b_std,
                                                            noise + (size_t)t * BDIM * SDIM);
        k3_reward<<<dim3(BDIM / BM, RHDIM / BN), 256, SM3>>>(parn, b_r1);
        k4_reduce<<<BDIM, 128>>>(parn, w_r2, b_r2, disc);
        disc *= 0.99f;
    }
    k_final<<<16, 256>>>(out);
}

// round 6
// speedup vs baseline: 1.5065x; 1.5065x over previous
#include <cuda_runtime.h>
#include <cuda_fp16.h>
#include <math.h>
#include <cstdint>

// Problem constants
#define BDIM 4096
#define HDIM 1024
#define SDIM 256
#define NSAMP 256
#define TSTEPS 10
#define RHDIM 512
#define N3 3072

// Tiling: BM=128, BN=32, BK=32 (halves), 8 warps x (16 rows x 32 cols)
#define BM 128
#define BN 32
#define AROW 20              // A smem row stride in words (32 halves + pad 8)
#define ASTG 2560            // A words per stage (128*20)
#define ABASE 7680           // 3 * ASTG
#define BROW 40              // B smem k2-row stride in words (32 + pad 8)
#define NB1 1920             // B words/stage k1 (3 gates * 16 * 40)
#define NB2 1280
#define NB3 640

// Persistent scratch
__device__ float g_h[2][BDIM * HDIM];
__device__ float g_s[BDIM * SDIM];
__device__ __half g_h16[2][BDIM * HDIM];
__device__ __half g_s16[BDIM * SDIM];
__device__ float g_relu[BDIM * RHDIM];
__device__ float g_acc[BDIM];
// Pre-packed half2 weights: word(k2) = (W[2k2][c], W[2k2+1][c]), c=(p&3)*8+(p>>2)
__device__ uint32_t W1h[32 * 40 * 3 * 16 * 32];   // [cb][kt][g][k2][p]
__device__ uint32_t W2h[8 * 32 * 2 * 16 * 32];
__device__ uint32_t W3h[16 * 40 * 16 * 32];

__device__ __forceinline__ float sigm_(float x) { return 1.0f / (1.0f + expf(-x)); }
__device__ __forceinline__ float softplus_(float x) {
    return fmaxf(x, 0.0f) + log1pf(expf(-fabsf(x)));
}
__device__ __forceinline__ uint32_t pack2(float lo, float hi) {
    __half2 h = __floats2half2_rn(lo, hi);
    return *(uint32_t*)&h;
}
__device__ __forceinline__ void mma_f16(float c[4], uint32_t a0, uint32_t a1,
                                        uint32_t a2, uint32_t a3,
                                        uint32_t b0, uint32_t b1) {
    asm volatile(
        "mma.sync.aligned.m16n8k16.row.col.f32.f16.f16.f32 "
        "{%0,%1,%2,%3},{%4,%5,%6,%7},{%8,%9},{%0,%1,%2,%3};\n"
        : "+f"(c[0]), "+f"(c[1]), "+f"(c[2]), "+f"(c[3])
        : "r"(a0), "r"(a1), "r"(a2), "r"(a3), "r"(b0), "r"(b1));
}
__device__ __forceinline__ void cp16(uint32_t dst, const void* src) {
    asm volatile("cp.async.cg.shared.global [%0], [%1], 16;" :: "r"(dst), "l"(src));
}
__device__ __forceinline__ void cp_commit() { asm volatile("cp.async.commit_group;"); }
template<int N> __device__ __forceinline__ void cp_wait() {
    asm volatile("cp.async.wait_group %0;" :: "n"(N));
}

// ---------------------------------------------------------------------------
// init + weight packing
// ---------------------------------------------------------------------------
__global__ void k_init(const float* __restrict__ h0, const float* __restrict__ s0) {
    int idx = blockIdx.x * blockDim.x + threadIdx.x;
    int stride = gridDim.x * blockDim.x;
    for (int i = idx; i < BDIM * HDIM; i += stride) {
        float v = h0[i & (HDIM - 1)];
        g_h[0][i] = v; g_h16[0][i] = __float2half_rn(v);
    }
    for (int i = idx; i < BDIM * SDIM; i += stride) {
        float v = s0[i & (SDIM - 1)];
        g_s[i] = v; g_s16[i] = __float2half_rn(v);
    }
    for (int i = idx; i < BDIM; i += stride) g_acc[i] = 0.0f;
}

__global__ void k_prep1(const float* __restrict__ Wx, const float* __restrict__ Wh) {
    const int total = 32 * 40 * 3 * 16 * 32;
    for (int idx = blockIdx.x * blockDim.x + threadIdx.x; idx < total;
         idx += gridDim.x * blockDim.x) {
        int p = idx & 31, k2 = (idx >> 5) & 15;
        int rest = idx >> 9;
        int g = rest % 3; rest /= 3;
        int kt = rest % 40; int cb = rest / 40;
        int c = (p & 3) * 8 + (p >> 2);
        int col = g * HDIM + cb * 32 + c;
        int row = kt * 32 + 2 * k2;
        float vlo, vhi;
        if (row < 256) { vlo = Wx[(size_t)row * N3 + col]; vhi = Wx[(size_t)(row + 1) * N3 + col]; }
        else { vlo = Wh[(size_t)(row - 256) * N3 + col]; vhi = Wh[(size_t)(row - 255) * N3 + col]; }
        W1h[idx] = pack2(vlo, vhi);
    }
}
__global__ void k_prep2(const float* __restrict__ W_mu, const float* __restrict__ W_std) {
    const int total = 8 * 32 * 2 * 16 * 32;
    for (int idx = blockIdx.x * blockDim.x + threadIdx.x; idx < total;
         idx += gridDim.x * blockDim.x) {
        int p = idx & 31, k2 = (idx >> 5) & 15;
        int rest = idx >> 9;
        int g = rest & 1; rest >>= 1;
        int kt = rest & 31; int cb = rest >> 5;
        int c = (p & 3) * 8 + (p >> 2);
        const float* W = g ? W_std : W_mu;
        int row = kt * 32 + 2 * k2;
        W2h[idx] = pack2(W[(size_t)row * SDIM + cb * 32 + c],
                         W[(size_t)(row + 1) * SDIM + cb * 32 + c]);
    }
}
__global__ void k_prep3(const float* __restrict__ W_r1) {
    const int total = 16 * 40 * 16 * 32;
    for (int idx = blockIdx.x * blockDim.x + threadIdx.x; idx < total;
         idx += gridDim.x * blockDim.x) {
        int p = idx & 31, k2 = (idx >> 5) & 15;
        int rest = idx >> 9;
        int kt = rest % 40; int cb = rest / 40;
        int c = (p & 3) * 8 + (p >> 2);
        int row = kt * 32 + 2 * k2;
        W3h[idx] = pack2(W_r1[(size_t)row * RHDIM + cb * 32 + c],
                         W_r1[(size_t)(row + 1) * RHDIM + cb * 32 + c]);
    }
}

// ---------------------------------------------------------------------------
// K1: GRU gates GEMM, fp16 mma, cp.async 3-stage. grid (32,32).
// ---------------------------------------------------------------------------
__global__ __launch_bounds__(256, 2)
void k1_gru(int par, const float* __restrict__ Wx,
            const float* __restrict__ b_gru, const int* __restrict__ acts_t) {
    extern __shared__ uint32_t smem[];
    const float* __restrict__ h_in = g_h[par];
    float* __restrict__ h_out = g_h[par ^ 1];
    const __half* __restrict__ h16_in = g_h16[par];
    __half* __restrict__ h16_out = g_h16[par ^ 1];

    const int tid = threadIdx.x, lane = tid & 31, warp = tid >> 5;
    const int row0 = blockIdx.x * BM, col0 = blockIdx.y * BN;
    const int wr = warp * 16;
    const uint32_t smem_b = (uint32_t)__cvta_generic_to_shared(smem);

    // A: 2 chunks/thread; rows tid>>2 and +64
    const int c4 = tid & 3, rA = tid >> 2;
    const int wA0 = rA * AROW + c4 * 4, wA1 = (rA + 64) * AROW + c4 * 4;
    const __half* sA = g_s16 + (size_t)(row0 + rA) * SDIM + c4 * 8;
    const __half* hA = h16_in + (size_t)(row0 + rA) * HDIM + c4 * 8;
    // B: chunk0 for all threads, chunk1 for tid<128
    const int bg0 = tid >> 7, bk0 = (tid >> 3) & 15, bc0 = tid & 7;
    const int wB0 = bg0 * 640 + bk0 * BROW + bc0 * 4;
    const int sB0w = bg0 * 512 + bk0 * 32 + bc0 * 4;
    const int wB1 = 2 * 640 + (tid >> 3) * BROW + (tid & 7) * 4;
    const int sB1w = 2 * 512 + (tid >> 3) * 32 + (tid & 7) * 4;
    const uint32_t* wblk = W1h + (size_t)blockIdx.y * (40 * 3 * 512);

#define K1_ISSUE(kt, s) do {                                                  \
    const __half* ap; int astr;                                               \
    if ((kt) < 8) { ap = sA + (kt) * 32; astr = SDIM; }                       \
    else { ap = hA + ((kt) - 8) * 32; astr = HDIM; }                          \
    cp16(smem_b + 4 * ((s) * ASTG + wA0), ap);                                \
    cp16(smem_b + 4 * ((s) * ASTG + wA1), ap + 64 * astr);                    \
    const uint32_t* wp = wblk + (size_t)(kt) * 1536;                          \
    cp16(smem_b + 4 * (ABASE + (s) * NB1 + wB0), wp + sB0w);                  \
    if (tid < 128) cp16(smem_b + 4 * (ABASE + (s) * NB1 + wB1), wp + sB1w);   \
    cp_commit(); } while (0)

    float acc[3][4][4], accNX[4][4];
#pragma unroll
    for (int g = 0; g < 3; g++)
#pragma unroll
        for (int nt = 0; nt < 4; nt++)
#pragma unroll
            for (int r = 0; r < 4; r++) acc[g][nt][r] = 0.0f;

    const int q = lane >> 2, klo = lane & 3;
    const int r1 = wr + q;
    const int a0w = r1 * AROW + klo, a1w = (r1 + 8) * AROW + klo;
    const int bfr = klo * BROW + q * 4;

    K1_ISSUE(0, 0);
    K1_ISSUE(1, 1);

    const int KT = 40;
#pragma unroll 1
    for (int kt = 0; kt < KT; ++kt) {
        if (kt + 1 < KT) cp_wait<1>(); else cp_wait<0>();
        __syncthreads();
        if (kt + 2 < KT) K1_ISSUE(kt + 2, (kt + 2) % 3);

        if (kt == 8) {
#pragma unroll
            for (int nt = 0; nt < 4; nt++)
#pragma unroll
                for (int r = 0; r < 4; r++) { accNX[nt][r] = acc[2][nt][r]; acc[2][nt][r] = 0.0f; }
        }
        const int sA_ = (kt % 3) * ASTG;
        const int sB_ = ABASE + (kt % 3) * NB1;
#pragma unroll
        for (int kc = 0; kc < 2; ++kc) {
            uint32_t a0 = smem[sA_ + a0w + 8 * kc];
            uint32_t a1 = smem[sA_ + a1w + 8 * kc];
            uint32_t a2 = smem[sA_ + a0w + 8 * kc + 4];
            uint32_t a3 = smem[sA_ + a1w + 8 * kc + 4];
#pragma unroll
            for (int g = 0; g < 3; g++) {
                const int bb = sB_ + g * 640 + 8 * kc * BROW + bfr;
                uint4 b0 = *(const uint4*)&smem[bb];
                uint4 b1 = *(const uint4*)&smem[bb + 4 * BROW];
                mma_f16(acc[g][0], a0, a1, a2, a3, b0.x, b1.x);
                mma_f16(acc[g][1], a0, a1, a2, a3, b0.y, b1.y);
                mma_f16(acc[g][2], a0, a1, a2, a3, b0.z, b1.z);
                mma_f16(acc[g][3], a0, a1, a2, a3, b0.w, b1.w);
            }
        }
    }
#undef K1_ISSUE

#pragma unroll
    for (int ri = 0; ri < 2; ri++) {
        int b = row0 + r1 + ri * 8;
        int a = acts_t[b];
        const float* wa = Wx + (size_t)(SDIM + a) * N3;
#pragma unroll
        for (int nt = 0; nt < 4; nt++) {
#pragma unroll
            for (int cj = 0; cj < 2; cj++) {
                int c = col0 + nt * 8 + 2 * klo + cj;
                int idx = ri * 2 + cj;
                float z = sigm_(acc[0][nt][idx] + wa[c] + b_gru[c]);
                float r = sigm_(acc[1][nt][idx] + wa[HDIM + c] + b_gru[HDIM + c]);
                float n = tanhf(accNX[nt][idx] + wa[2 * HDIM + c]
                                + r * acc[2][nt][idx] + b_gru[2 * HDIM + c]);
                float hp = h_in[(size_t)b * HDIM + c];
                float hv = (1.0f - z) * hp + z * n;
                h_out[(size_t)b * HDIM + c] = hv;
                h16_out[(size_t)b * HDIM + c] = __float2half_rn(hv);
            }
        }
    }
}

// ---------------------------------------------------------------------------
// K2: mu/std GEMM + latent sample. grid (32,8).
// ---------------------------------------------------------------------------
__global__ __launch_bounds__(256, 2)
void k2_latent(int parn, const float* __restrict__ b_mu, const float* __restrict__ b_std,
               const float* __restrict__ noise_t) {
    extern __shared__ uint32_t smem[];
    const __half* __restrict__ h16 = g_h16[parn];

    const int tid = threadIdx.x, lane = tid & 31, warp = tid >> 5;
    const int row0 = blockIdx.x * BM, col0 = blockIdx.y * BN;
    const int wr = warp * 16;
    const uint32_t smem_b = (uint32_t)__cvta_generic_to_shared(smem);

    const int c4 = tid & 3, rA = tid >> 2;
    const int wA0 = rA * AROW + c4 * 4, wA1 = (rA + 64) * AROW + c4 * 4;
    const __half* hA = h16 + (size_t)(row0 + rA) * HDIM + c4 * 8;
    const int bg0 = tid >> 7, bk0 = (tid >> 3) & 15, bc0 = tid & 7;
    const int wB0 = bg0 * 640 + bk0 * BROW + bc0 * 4;
    const int sB0w = bg0 * 512 + bk0 * 32 + bc0 * 4;
    const uint32_t* wblk = W2h + (size_t)blockIdx.y * (32 * 2 * 512);

#define K2_ISSUE(kt, s) do {                                                  \
    const __half* ap = hA + (kt) * 32;                                        \
    cp16(smem_b + 4 * ((s) * ASTG + wA0), ap);                                \
    cp16(smem_b + 4 * ((s) * ASTG + wA1), ap + 64 * HDIM);                    \
    const uint32_t* wp = wblk + (size_t)(kt) * 1024;                          \
    cp16(smem_b + 4 * (ABASE + (s) * NB2 + wB0), wp + sB0w);                  \
    cp_commit(); } while (0)

    float acc[2][4][4];
#pragma unroll
    for (int g = 0; g < 2; g++)
#pragma unroll
        for (int nt = 0; nt < 4; nt++)
#pragma unroll
            for (int r = 0; r < 4; r++) acc[g][nt][r] = 0.0f;

    const int q = lane >> 2, klo = lane & 3;
    const int r1 = wr + q;
    const int a0w = r1 * AROW + klo, a1w = (r1 + 8) * AROW + klo;
    const int bfr = klo * BROW + q * 4;

    K2_ISSUE(0, 0);
    K2_ISSUE(1, 1);

    const int KT = 32;
#pragma unroll 1
    for (int kt = 0; kt < KT; ++kt) {
        if (kt + 1 < KT) cp_wait<1>(); else cp_wait<0>();
        __syncthreads();
        if (kt + 2 < KT) K2_ISSUE(kt + 2, (kt + 2) % 3);

        const int sA_ = (kt % 3) * ASTG;
        const int sB_ = ABASE + (kt % 3) * NB2;
#pragma unroll
        for (int kc = 0; kc < 2; ++kc) {
            uint32_t a0 = smem[sA_ + a0w + 8 * kc];
            uint32_t a1 = smem[sA_ + a1w + 8 * kc];
            uint32_t a2 = smem[sA_ + a0w + 8 * kc + 4];
            uint32_t a3 = smem[sA_ + a1w + 8 * kc + 4];
#pragma unroll
            for (int g = 0; g < 2; g++) {
                const int bb = sB_ + g * 640 + 8 * kc * BROW + bfr;
                uint4 b0 = *(const uint4*)&smem[bb];
                uint4 b1 = *(const uint4*)&smem[bb + 4 * BROW];
                mma_f16(acc[g][0], a0, a1, a2, a3, b0.x, b1.x);
                mma_f16(acc[g][1], a0, a1, a2, a3, b0.y, b1.y);
                mma_f16(acc[g][2], a0, a1, a2, a3, b0.z, b1.z);
                mma_f16(acc[g][3], a0, a1, a2, a3, b0.w, b1.w);
            }
        }
    }
#undef K2_ISSUE

#pragma unroll
    for (int ri = 0; ri < 2; ri++) {
        int b = row0 + r1 + ri * 8;
#pragma unroll
        for (int nt = 0; nt < 4; nt++) {
#pragma unroll
            for (int cj = 0; cj < 2; cj++) {
                int c = col0 + nt * 8 + 2 * klo + cj;
                int idx = ri * 2 + cj;
                float mu = acc[0][nt][idx] + b_mu[c];
                float sd = softplus_(acc[1][nt][idx] + b_std[c]) + 0.1f;
                float sv = mu + sd * noise_t[(size_t)b * SDIM + c];
                g_s[(size_t)b * SDIM + c] = sv;
                g_s16[(size_t)b * SDIM + c] = __float2half_rn(sv);
            }
        }
    }
}

// ---------------------------------------------------------------------------
// K3: reward hidden GEMM + ReLU. grid (32,16). K=1280 split at 1024.
// ---------------------------------------------------------------------------
__global__ __launch_bounds__(256, 2)
void k3_reward(int parn, const float* __restrict__ b_r1) {
    extern __shared__ uint32_t smem[];
    const __half* __restrict__ h16 = g_h16[parn];

    const int tid = threadIdx.x, lane = tid & 31, warp = tid >> 5;
    const int row0 = blockIdx.x * BM, col0 = blockIdx.y * BN;
    const int wr = warp * 16;
    const uint32_t smem_b = (uint32_t)__cvta_generic_to_shared(smem);

    const int c4 = tid & 3, rA = tid >> 2;
    const int wA0 = rA * AROW + c4 * 4, wA1 = (rA + 64) * AROW + c4 * 4;
    const __half* hA = h16 + (size_t)(row0 + rA) * HDIM + c4 * 8;
    const __half* sA = g_s16 + (size_t)(row0 + rA) * SDIM + c4 * 8;
    const int wB0 = (tid >> 3) * BROW + (tid & 7) * 4;   // tid<128 only
    const int sB0w = (tid >> 3) * 32 + (tid & 7) * 4;
    const uint32_t* wblk = W3h + (size_t)blockIdx.y * (40 * 512);

#define K3_ISSUE(kt, s) do {                                                  \
    const __half* ap; int astr;                                               \
    if ((kt) < 32) { ap = hA + (kt) * 32; astr = HDIM; }                      \
    else { ap = sA + ((kt) - 32) * 32; astr = SDIM; }                         \
    cp16(smem_b + 4 * ((s) * ASTG + wA0), ap);                                \
    cp16(smem_b + 4 * ((s) * ASTG + wA1), ap + 64 * astr);                    \
    if (tid < 128)                                                            \
        cp16(smem_b + 4 * (ABASE + (s) * NB3 + wB0), wblk + (size_t)(kt) * 512 + sB0w); \
    cp_commit(); } while (0)

    float acc[4][4];
#pragma unroll
    for (int nt = 0; nt < 4; nt++)
#pragma unroll
        for (int r = 0; r < 4; r++) acc[nt][r] = 0.0f;

    const int q = lane >> 2, klo = lane & 3;
    const int r1 = wr + q;
    const int a0w = r1 * AROW + klo, a1w = (r1 + 8) * AROW + klo;
    const int bfr = klo * BROW + q * 4;

    K3_ISSUE(0, 0);
    K3_ISSUE(1, 1);

    const int KT = 40;
#pragma unroll 1
    for (int kt = 0; kt < KT; ++kt) {
        if (kt + 1 < KT) cp_wait<1>(); else cp_wait<0>();
        __syncthreads();
        if (kt + 2 < KT) K3_ISSUE(kt + 2, (kt + 2) % 3);

        const int sA_ = (kt % 3) * ASTG;
        const int sB_ = ABASE + (kt % 3) * NB3;
#pragma unroll
        for (int kc = 0; kc < 2; ++kc) {
            uint32_t a0 = smem[sA_ + a0w + 8 * kc];
            uint32_t a1 = smem[sA_ + a1w + 8 * kc];
            uint32_t a2 = smem[sA_ + a0w + 8 * kc + 4];
            uint32_t a3 = smem[sA_ + a1w + 8 * kc + 4];
            const int bb = sB_ + 8 * kc * BROW + bfr;
            uint4 b0 = *(const uint4*)&smem[bb];
            uint4 b1 = *(const uint4*)&smem[bb + 4 * BROW];
            mma_f16(acc[0], a0, a1, a2, a3, b0.x, b1.x);
            mma_f16(acc[1], a0, a1, a2, a3, b0.y, b1.y);
            mma_f16(acc[2], a0, a1, a2, a3, b0.z, b1.z);
            mma_f16(acc[3], a0, a1, a2, a3, b0.w, b1.w);
        }
    }
#undef K3_ISSUE

#pragma unroll
    for (int ri = 0; ri < 2; ri++) {
        int b = row0 + r1 + ri * 8;
#pragma unroll
        for (int nt = 0; nt < 4; nt++) {
#pragma unroll
            for (int cj = 0; cj < 2; cj++) {
                int c = col0 + nt * 8 + 2 * klo + cj;
                int idx = ri * 2 + cj;
                g_relu[(size_t)b * RHDIM + c] = fmaxf(acc[nt][idx] + b_r1[c], 0.0f);
            }
        }
    }
}

// ---------------------------------------------------------------------------
// K4 + final reductions
// ---------------------------------------------------------------------------
__global__ void k4_reduce(int parn, const float* __restrict__ w_r2,
                          const float* __restrict__ b_r2, float disc) {
    const int b = blockIdx.x;
    const int tid = threadIdx.x;
    const float* __restrict__ hr = g_h[parn] + (size_t)b * HDIM;
    const float* __restrict__ sr = g_s + (size_t)b * SDIM;
    const float* __restrict__ rr = g_relu + (size_t)b * RHDIM;

    float sum = 0.0f, sq = 0.0f, dot = 0.0f;
    for (int k = tid; k < HDIM; k += 128) { float v = hr[k]; sum += v; sq = fmaf(v, v, sq); }
    for (int k = tid; k < SDIM; k += 128) { float v = sr[k]; sum += v; sq = fmaf(v, v, sq); }
    for (int k = tid; k < RHDIM; k += 128) dot = fmaf(rr[k], w_r2[k], dot);

#pragma unroll
    for (int off = 16; off > 0; off >>= 1) {
        sum += __shfl_down_sync(0xffffffffu, sum, off);
        sq  += __shfl_down_sync(0xffffffffu, sq, off);
        dot += __shfl_down_sync(0xffffffffu, dot, off);
    }
    __shared__ float s1[4], s2[4], s3[4];
    if ((tid & 31) == 0) { s1[tid >> 5] = sum; s2[tid >> 5] = sq; s3[tid >> 5] = dot; }
    __syncthreads();
    if (tid == 0) {
        float S = s1[0] + s1[1] + s1[2] + s1[3];
        float Q = s2[0] + s2[1] + s2[2] + s2[3];
        float D = s3[0] + s3[1] + s3[2] + s3[3];
        float mean = S * (1.0f / 1280.0f);
        float var = Q * (1.0f / 1280.0f) - mean * mean;
        g_acc[b] += disc * ((D + b_r2[0]) + var);
    }
}

__global__ void k_final(float* __restrict__ out) {
    const int a = blockIdx.x;
    const int tid = threadIdx.x;
    float v = g_acc[a * NSAMP + tid];
#pragma unroll
    for (int off = 16; off > 0; off >>= 1) v += __shfl_down_sync(0xffffffffu, v, off);
    __shared__ float w[8];
    if ((tid & 31) == 0) w[tid >> 5] = v;
    __syncthreads();
    if (tid < 8) {
        float x = w[tid];
#pragma unroll
        for (int off = 4; off > 0; off >>= 1) x += __shfl_down_sync(0xffu, x, off);
        if (tid == 0) out[a] = -x * (1.0f / (float)NSAMP);
    }
}

// ---------------------------------------------------------------------------
extern "C" void kernel_launch(void* const* d_in, const int* in_sizes, int n_in,
                              void* d_out, int out_size) {
    (void)in_sizes; (void)n_in; (void)out_size;
    const float* h0    = (const float*)d_in[0];
    const float* s0    = (const float*)d_in[1];
    const float* noise = (const float*)d_in[2];
    const float* Wx    = (const float*)d_in[3];
    const float* Wh    = (const float*)d_in[4];
    const float* b_gru = (const float*)d_in[5];
    const float* W_mu  = (const float*)d_in[6];
    const float* b_mu  = (const float*)d_in[7];
    const float* W_std = (const float*)d_in[8];
    const float* b_std = (const float*)d_in[9];
    const float* W_r1  = (const float*)d_in[10];
    const float* b_r1  = (const float*)d_in[11];
    const float* w_r2  = (const float*)d_in[12];
    const float* b_r2  = (const float*)d_in[13];
    const int*   acts  = (const int*)d_in[14];
    float* out = (float*)d_out;

    const int SM1 = (ABASE + 3 * NB1) * 4;   // 53760 B
    const int SM2 = (ABASE + 3 * NB2) * 4;   // 46080 B
    const int SM3 = (ABASE + 3 * NB3) * 4;   // 38400 B
    cudaFuncSetAttribute(k1_gru, cudaFuncAttributeMaxDynamicSharedMemorySize, SM1);
    cudaFuncSetAttribute(k2_latent, cudaFuncAttributeMaxDynamicSharedMemorySize, SM2);
    cudaFuncSetAttribute(k3_reward, cudaFuncAttributeMaxDynamicSharedMemorySize, SM3);

    k_init<<<512, 256>>>(h0, s0);
    k_prep1<<<2048, 256>>>(Wx, Wh);
    k_prep2<<<256, 256>>>(W_mu, W_std);
    k_prep3<<<320, 256>>>(W_r1);

    float disc = 1.0f;
    for (int t = 0; t < TSTEPS; ++t) {
        int par = t & 1;
        int parn = par ^ 1;
        k1_gru<<<dim3(BDIM / BM, HDIM / BN), 256, SM1>>>(par, Wx, b_gru, acts + (size_t)t * BDIM);
        k2_latent<<<dim3(BDIM / BM, SDIM / BN), 256, SM2>>>(parn, b_mu, b_std,
                                                            noise + (size_t)t * BDIM * SDIM);
        k3_reward<<<dim3(BDIM / BM, RHDIM / BN), 256, SM3>>>(parn, b_r1);
        k4_reduce<<<BDIM, 128>>>(parn, w_r2, b_r2, disc);
        disc *= 0.99f;
    }
    k_final<<<16, 256>>>(out);
}

// round 8
// speedup vs baseline: 1.5977x; 1.0606x over previous
#include <cuda_runtime.h>
#include <cuda_fp16.h>
#include <math.h>
#include <cstdint>

// Problem constants
#define BDIM 4096
#define HDIM 1024
#define SDIM 256
#define NSAMP 256
#define TSTEPS 10
#define RHDIM 512
#define N3 3072

// Tiling: BM=128, BN=32, BK=32 (halves), 8 warps x (16 rows x 32 cols)
#define BM 128
#define BN 32
#define AROW 20              // A smem row stride in words (32 halves + pad 8)
#define ASTG 2560            // A words per stage (128*20)
#define ABASE 7680           // 3 * ASTG
#define BROW 40              // B smem k2-row stride in words
#define NB1 1920
#define NB2 1280
#define NB3 640

// Persistent scratch
__device__ float g_h[2][BDIM * HDIM];
__device__ float g_s[BDIM * SDIM];
__device__ __half g_h16[2][BDIM * HDIM];
__device__ __half g_s16[BDIM * SDIM];
__device__ float g_acc[BDIM];
// per-step per-CTA-column partial sums (deterministic, no atomics)
__device__ float g_hS[TSTEPS * 32 * BDIM];
__device__ float g_hQ[TSTEPS * 32 * BDIM];
__device__ float g_sS[TSTEPS * 8 * BDIM];
__device__ float g_sQ[TSTEPS * 8 * BDIM];
__device__ float g_rD[TSTEPS * 16 * BDIM];
// Pre-packed half2 weights: word(k2) = (W[2k2][c], W[2k2+1][c]), c=(p&3)*8+(p>>2)
__device__ uint32_t W1h[32 * 40 * 3 * 16 * 32];
__device__ uint32_t W2h[8 * 32 * 2 * 16 * 32];
__device__ uint32_t W3h[16 * 40 * 16 * 32];

__device__ __forceinline__ float sigm_(float x) { return 1.0f / (1.0f + expf(-x)); }
__device__ __forceinline__ float softplus_(float x) {
    return fmaxf(x, 0.0f) + log1pf(expf(-fabsf(x)));
}
__device__ __forceinline__ uint32_t pack2(float lo, float hi) {
    __half2 h = __floats2half2_rn(lo, hi);
    return *(uint32_t*)&h;
}
__device__ __forceinline__ float red4(float v) {
    v += __shfl_xor_sync(0xffffffffu, v, 1);
    v += __shfl_xor_sync(0xffffffffu, v, 2);
    return v;
}
__device__ __forceinline__ void mma_f16(float c[4], uint32_t a0, uint32_t a1,
                                        uint32_t a2, uint32_t a3,
                                        uint32_t b0, uint32_t b1) {
    asm volatile(
        "mma.sync.aligned.m16n8k16.row.col.f32.f16.f16.f32 "
        "{%0,%1,%2,%3},{%4,%5,%6,%7},{%8,%9},{%0,%1,%2,%3};\n"
        : "+f"(c[0]), "+f"(c[1]), "+f"(c[2]), "+f"(c[3])
        : "r"(a0), "r"(a1), "r"(a2), "r"(a3), "r"(b0), "r"(b1));
}
__device__ __forceinline__ void ldsm4(uint32_t& r0, uint32_t& r1, uint32_t& r2,
                                      uint32_t& r3, uint32_t addr) {
    asm volatile("ldmatrix.sync.aligned.m8n8.x4.shared.b16 {%0,%1,%2,%3}, [%4];"
                 : "=r"(r0), "=r"(r1), "=r"(r2), "=r"(r3) : "r"(addr));
}
__device__ __forceinline__ void cp16(uint32_t dst, const void* src) {
    asm volatile("cp.async.cg.shared.global [%0], [%1], 16;" :: "r"(dst), "l"(src));
}
__device__ __forceinline__ void cp_commit() { asm volatile("cp.async.commit_group;"); }
template<int N> __device__ __forceinline__ void cp_wait() {
    asm volatile("cp.async.wait_group %0;" :: "n"(N));
}

// ---------------------------------------------------------------------------
// init + weight packing
// ---------------------------------------------------------------------------
__global__ void k_init(const float* __restrict__ h0, const float* __restrict__ s0) {
    int idx = blockIdx.x * blockDim.x + threadIdx.x;
    int stride = gridDim.x * blockDim.x;
    for (int i = idx; i < BDIM * HDIM; i += stride) {
        float v = h0[i & (HDIM - 1)];
        g_h[0][i] = v; g_h16[0][i] = __float2half_rn(v);
    }
    for (int i = idx; i < BDIM * SDIM; i += stride) {
        float v = s0[i & (SDIM - 1)];
        g_s[i] = v; g_s16[i] = __float2half_rn(v);
    }
}

__global__ void k_prep1(const float* __restrict__ Wx, const float* __restrict__ Wh) {
    const int total = 32 * 40 * 3 * 16 * 32;
    for (int idx = blockIdx.x * blockDim.x + threadIdx.x; idx < total;
         idx += gridDim.x * blockDim.x) {
        int p = idx & 31, k2 = (idx >> 5) & 15;
        int rest = idx >> 9;
        int g = rest % 3; rest /= 3;
        int kt = rest % 40; int cb = rest / 40;
        int c = (p & 3) * 8 + (p >> 2);
        int col = g * HDIM + cb * 32 + c;
        int row = kt * 32 + 2 * k2;
        float vlo, vhi;
        if (row < 256) { vlo = Wx[(size_t)row * N3 + col]; vhi = Wx[(size_t)(row + 1) * N3 + col]; }
        else { vlo = Wh[(size_t)(row - 256) * N3 + col]; vhi = Wh[(size_t)(row - 255) * N3 + col]; }
        W1h[idx] = pack2(vlo, vhi);
    }
}
__global__ void k_prep2(const float* __restrict__ W_mu, const float* __restrict__ W_std) {
    const int total = 8 * 32 * 2 * 16 * 32;
    for (int idx = blockIdx.x * blockDim.x + threadIdx.x; idx < total;
         idx += gridDim.x * blockDim.x) {
        int p = idx & 31, k2 = (idx >> 5) & 15;
        int rest = idx >> 9;
        int g = rest & 1; rest >>= 1;
        int kt = rest & 31; int cb = rest >> 5;
        int c = (p & 3) * 8 + (p >> 2);
        const float* W = g ? W_std : W_mu;
        int row = kt * 32 + 2 * k2;
        W2h[idx] = pack2(W[(size_t)row * SDIM + cb * 32 + c],
                         W[(size_t)(row + 1) * SDIM + cb * 32 + c]);
    }
}
__global__ void k_prep3(const float* __restrict__ W_r1) {
    const int total = 16 * 40 * 16 * 32;
    for (int idx = blockIdx.x * blockDim.x + threadIdx.x; idx < total;
         idx += gridDim.x * blockDim.x) {
        int p = idx & 31, k2 = (idx >> 5) & 15;
        int rest = idx >> 9;
        int kt = rest % 40; int cb = rest / 40;
        int c = (p & 3) * 8 + (p >> 2);
        int row = kt * 32 + 2 * k2;
        W3h[idx] = pack2(W_r1[(size_t)row * RHDIM + cb * 32 + c],
                         W_r1[(size_t)(row + 1) * RHDIM + cb * 32 + c]);
    }
}

// ---------------------------------------------------------------------------
// K1: GRU gates GEMM, fp16 mma + ldmatrix, cp.async 3-stage. grid (32,32).
// ---------------------------------------------------------------------------
__global__ __launch_bounds__(256, 2)
void k1_gru(int par, int t, const float* __restrict__ Wx,
            const float* __restrict__ b_gru, const int* __restrict__ acts_t) {
    extern __shared__ uint32_t smem[];
    const float* __restrict__ h_in = g_h[par];
    float* __restrict__ h_out = g_h[par ^ 1];
    const __half* __restrict__ h16_in = g_h16[par];
    __half* __restrict__ h16_out = g_h16[par ^ 1];

    const int tid = threadIdx.x, lane = tid & 31, warp = tid >> 5;
    const int row0 = blockIdx.x * BM, col0 = blockIdx.y * BN, by = blockIdx.y;
    const int wr = warp * 16;
    const uint32_t smem_b = (uint32_t)__cvta_generic_to_shared(smem);

    const int c4 = tid & 3, rA = tid >> 2;
    const int wA0 = rA * AROW + c4 * 4, wA1 = (rA + 64) * AROW + c4 * 4;
    const __half* sA = g_s16 + (size_t)(row0 + rA) * SDIM + c4 * 8;
    const __half* hA = h16_in + (size_t)(row0 + rA) * HDIM + c4 * 8;
    const int bg0 = tid >> 7, bk0 = (tid >> 3) & 15, bc0 = tid & 7;
    const int wB0 = bg0 * 640 + bk0 * BROW + bc0 * 4;
    const int sB0w = bg0 * 512 + bk0 * 32 + bc0 * 4;
    const int wB1 = 2 * 640 + (tid >> 3) * BROW + (tid & 7) * 4;
    const int sB1w = 2 * 512 + (tid >> 3) * 32 + (tid & 7) * 4;
    const uint32_t* wblk = W1h + (size_t)blockIdx.y * (40 * 3 * 512);

#define K1_ISSUE(kt, s) do {                                                  \
    const __half* ap; int astr;                                               \
    if ((kt) < 8) { ap = sA + (kt) * 32; astr = SDIM; }                       \
    else { ap = hA + ((kt) - 8) * 32; astr = HDIM; }                          \
    cp16(smem_b + 4 * ((s) * ASTG + wA0), ap);                                \
    cp16(smem_b + 4 * ((s) * ASTG + wA1), ap + 64 * astr);                    \
    const uint32_t* wp = wblk + (size_t)(kt) * 1536;                          \
    cp16(smem_b + 4 * (ABASE + (s) * NB1 + wB0), wp + sB0w);                  \
    if (tid < 128) cp16(smem_b + 4 * (ABASE + (s) * NB1 + wB1), wp + sB1w);   \
    cp_commit(); } while (0)

    float acc[3][4][4], accNX[4][4];
#pragma unroll
    for (int g = 0; g < 3; g++)
#pragma unroll
        for (int nt = 0; nt < 4; nt++)
#pragma unroll
            for (int r = 0; r < 4; r++) acc[g][nt][r] = 0.0f;

    const int q = lane >> 2, klo = lane & 3;
    const int r1 = wr + q;
    const int bfr = klo * BROW + q * 4;
    // ldmatrix per-lane base (bytes): row wr+(lane&15), k-half offset (lane>>4)*16B
    const uint32_t aBase = smem_b + (uint32_t)(wr + (lane & 15)) * AROW * 4
                         + ((lane >> 4) * 16);

    K1_ISSUE(0, 0);
    K1_ISSUE(1, 1);

    const int KT = 40;
#pragma unroll 1
    for (int kt = 0; kt < KT; ++kt) {
        if (kt + 1 < KT) cp_wait<1>(); else cp_wait<0>();
        __syncthreads();
        if (kt + 2 < KT) K1_ISSUE(kt + 2, (kt + 2) % 3);

        if (kt == 8) {
#pragma unroll
            for (int nt = 0; nt < 4; nt++)
#pragma unroll
                for (int r = 0; r < 4; r++) { accNX[nt][r] = acc[2][nt][r]; acc[2][nt][r] = 0.0f; }
        }
        const int sA_ = (kt % 3) * ASTG;
        const int sB_ = ABASE + (kt % 3) * NB1;
#pragma unroll
        for (int kc = 0; kc < 2; ++kc) {
            uint32_t a0, a1, a2, a3;
            ldsm4(a0, a1, a2, a3, aBase + 4 * sA_ + kc * 32);
#pragma unroll
            for (int g = 0; g < 3; g++) {
                const int bb = sB_ + g * 640 + 8 * kc * BROW + bfr;
                uint4 b0 = *(const uint4*)&smem[bb];
                uint4 b1 = *(const uint4*)&smem[bb + 4 * BROW];
                mma_f16(acc[g][0], a0, a1, a2, a3, b0.x, b1.x);
                mma_f16(acc[g][1], a0, a1, a2, a3, b0.y, b1.y);
                mma_f16(acc[g][2], a0, a1, a2, a3, b0.z, b1.z);
                mma_f16(acc[g][3], a0, a1, a2, a3, b0.w, b1.w);
            }
        }
    }
#undef K1_ISSUE

    float sumr[2] = {0.0f, 0.0f}, sqr[2] = {0.0f, 0.0f};
#pragma unroll
    for (int ri = 0; ri < 2; ri++) {
        int b = row0 + r1 + ri * 8;
        int a = acts_t[b];
        const float* wa = Wx + (size_t)(SDIM + a) * N3;
#pragma unroll
        for (int nt = 0; nt < 4; nt++) {
#pragma unroll
            for (int cj = 0; cj < 2; cj++) {
                int c = col0 + nt * 8 + 2 * klo + cj;
                int idx = ri * 2 + cj;
                float z = sigm_(acc[0][nt][idx] + wa[c] + b_gru[c]);
                float r = sigm_(acc[1][nt][idx] + wa[HDIM + c] + b_gru[HDIM + c]);
                float n = tanhf(accNX[nt][idx] + wa[2 * HDIM + c]
                                + r * acc[2][nt][idx] + b_gru[2 * HDIM + c]);
                float hp = h_in[(size_t)b * HDIM + c];
                float hv = (1.0f - z) * hp + z * n;
                h_out[(size_t)b * HDIM + c] = hv;
                h16_out[(size_t)b * HDIM + c] = __float2half_rn(hv);
                sumr[ri] += hv;
                sqr[ri] = fmaf(hv, hv, sqr[ri]);
            }
        }
    }
#pragma unroll
    for (int ri = 0; ri < 2; ri++) {
        float S = red4(sumr[ri]);
        float Q = red4(sqr[ri]);
        if (klo == 0) {
            int b = row0 + r1 + ri * 8;
            g_hS[(size_t)(t * 32 + by) * BDIM + b] = S;
            g_hQ[(size_t)(t * 32 + by) * BDIM + b] = Q;
        }
    }
}

// ---------------------------------------------------------------------------
// K2: mu/std GEMM + latent sample + s partial sums. grid (32,8).
// ---------------------------------------------------------------------------
__global__ __launch_bounds__(256, 2)
void k2_latent(int parn, int t, const float* __restrict__ b_mu,
               const float* __restrict__ b_std, const float* __restrict__ noise_t) {
    extern __shared__ uint32_t smem[];
    const __half* __restrict__ h16 = g_h16[parn];

    const int tid = threadIdx.x, lane = tid & 31, warp = tid >> 5;
    const int row0 = blockIdx.x * BM, col0 = blockIdx.y * BN, by = blockIdx.y;
    const int wr = warp * 16;
    const uint32_t smem_b = (uint32_t)__cvta_generic_to_shared(smem);

    const int c4 = tid & 3, rA = tid >> 2;
    const int wA0 = rA * AROW + c4 * 4, wA1 = (rA + 64) * AROW + c4 * 4;
    const __half* hA = h16 + (size_t)(row0 + rA) * HDIM + c4 * 8;
    const int bg0 = tid >> 7, bk0 = (tid >> 3) & 15, bc0 = tid & 7;
    const int wB0 = bg0 * 640 + bk0 * BROW + bc0 * 4;
    const int sB0w = bg0 * 512 + bk0 * 32 + bc0 * 4;
    const uint32_t* wblk = W2h + (size_t)blockIdx.y * (32 * 2 * 512);

#define K2_ISSUE(kt, s) do {                                                  \
    const __half* ap = hA + (kt) * 32;                                        \
    cp16(smem_b + 4 * ((s) * ASTG + wA0), ap);                                \
    cp16(smem_b + 4 * ((s) * ASTG + wA1), ap + 64 * HDIM);                    \
    const uint32_t* wp = wblk + (size_t)(kt) * 1024;                          \
    cp16(smem_b + 4 * (ABASE + (s) * NB2 + wB0), wp + sB0w);                  \
    cp_commit(); } while (0)

    float acc[2][4][4];
#pragma unroll
    for (int g = 0; g < 2; g++)
#pragma unroll
        for (int nt = 0; nt < 4; nt++)
#pragma unroll
            for (int r = 0; r < 4; r++) acc[g][nt][r] = 0.0f;

    const int q = lane >> 2, klo = lane & 3;
    const int r1 = wr + q;
    const int bfr = klo * BROW + q * 4;
    const uint32_t aBase = smem_b + (uint32_t)(wr + (lane & 15)) * AROW * 4
                         + ((lane >> 4) * 16);

    K2_ISSUE(0, 0);
    K2_ISSUE(1, 1);

    const int KT = 32;
#pragma unroll 1
    for (int kt = 0; kt < KT; ++kt) {
        if (kt + 1 < KT) cp_wait<1>(); else cp_wait<0>();
        __syncthreads();
        if (kt + 2 < KT) K2_ISSUE(kt + 2, (kt + 2) % 3);

        const int sA_ = (kt % 3) * ASTG;
        const int sB_ = ABASE + (kt % 3) * NB2;
#pragma unroll
        for (int kc = 0; kc < 2; ++kc) {
            uint32_t a0, a1, a2, a3;
            ldsm4(a0, a1, a2, a3, aBase + 4 * sA_ + kc * 32);
#pragma unroll
            for (int g = 0; g < 2; g++) {
                const int bb = sB_ + g * 640 + 8 * kc * BROW + bfr;
                uint4 b0 = *(const uint4*)&smem[bb];
                uint4 b1 = *(const uint4*)&smem[bb + 4 * BROW];
                mma_f16(acc[g][0], a0, a1, a2, a3, b0.x, b1.x);
                mma_f16(acc[g][1], a0, a1, a2, a3, b0.y, b1.y);
                mma_f16(acc[g][2], a0, a1, a2, a3, b0.z, b1.z);
                mma_f16(acc[g][3], a0, a1, a2, a3, b0.w, b1.w);
            }
        }
    }
#undef K2_ISSUE

    float sumr[2] = {0.0f, 0.0f}, sqr[2] = {0.0f, 0.0f};
#pragma unroll
    for (int ri = 0; ri < 2; ri++) {
        int b = row0 + r1 + ri * 8;
#pragma unroll
        for (int nt = 0; nt < 4; nt++) {
#pragma unroll
            for (int cj = 0; cj < 2; cj++) {
                int c = col0 + nt * 8 + 2 * klo + cj;
                int idx = ri * 2 + cj;
                float mu = acc[0][nt][idx] + b_mu[c];
                float sd = softplus_(acc[1][nt][idx] + b_std[c]) + 0.1f;
                float sv = mu + sd * noise_t[(size_t)b * SDIM + c];
                g_s[(size_t)b * SDIM + c] = sv;
                g_s16[(size_t)b * SDIM + c] = __float2half_rn(sv);
                sumr[ri] += sv;
                sqr[ri] = fmaf(sv, sv, sqr[ri]);
            }
        }
    }
#pragma unroll
    for (int ri = 0; ri < 2; ri++) {
        float S = red4(sumr[ri]);
        float Q = red4(sqr[ri]);
        if (klo == 0) {
            int b = row0 + r1 + ri * 8;
            g_sS[(size_t)(t * 8 + by) * BDIM + b] = S;
            g_sQ[(size_t)(t * 8 + by) * BDIM + b] = Q;
        }
    }
}

// ---------------------------------------------------------------------------
// K3: reward hidden GEMM + fused relu . w_r2 partial dot. grid (32,16).
// ---------------------------------------------------------------------------
__global__ __launch_bounds__(256, 2)
void k3_reward(int parn, int t, const float* __restrict__ b_r1,
               const float* __restrict__ w_r2) {
    extern __shared__ uint32_t smem[];
    const __half* __restrict__ h16 = g_h16[parn];

    const int tid = threadIdx.x, lane = tid & 31, warp = tid >> 5;
    const int row0 = blockIdx.x * BM, col0 = blockIdx.y * BN, by = blockIdx.y;
    const int wr = warp * 16;
    const uint32_t smem_b = (uint32_t)__cvta_generic_to_shared(smem);

    const int c4 = tid & 3, rA = tid >> 2;
    const int wA0 = rA * AROW + c4 * 4, wA1 = (rA + 64) * AROW + c4 * 4;
    const __half* hA = h16 + (size_t)(row0 + rA) * HDIM + c4 * 8;
    const __half* sA = g_s16 + (size_t)(row0 + rA) * SDIM + c4 * 8;
    const int wB0 = (tid >> 3) * BROW + (tid & 7) * 4;
    const int sB0w = (tid >> 3) * 32 + (tid & 7) * 4;
    const uint32_t* wblk = W3h + (size_t)blockIdx.y * (40 * 512);

#define K3_ISSUE(kt, s) do {                                                  \
    const __half* ap; int astr;                                               \
    if ((kt) < 32) { ap = hA + (kt) * 32; astr = HDIM; }                      \
    else { ap = sA + ((kt) - 32) * 32; astr = SDIM; }                         \
    cp16(smem_b + 4 * ((s) * ASTG + wA0), ap);                                \
    cp16(smem_b + 4 * ((s) * ASTG + wA1), ap + 64 * astr);                    \
    if (tid < 128)                                                            \
        cp16(smem_b + 4 * (ABASE + (s) * NB3 + wB0), wblk + (size_t)(kt) * 512 + sB0w); \
    cp_commit(); } while (0)

    float acc[4][4];
#pragma unroll
    for (int nt = 0; nt < 4; nt++)
#pragma unroll
        for (int r = 0; r < 4; r++) acc[nt][r] = 0.0f;

    const int q = lane >> 2, klo = lane & 3;
    const int r1 = wr + q;
    const int bfr = klo * BROW + q * 4;
    const uint32_t aBase = smem_b + (uint32_t)(wr + (lane & 15)) * AROW * 4
                         + ((lane >> 4) * 16);

    K3_ISSUE(0, 0);
    K3_ISSUE(1, 1);

    const int KT = 40;
#pragma unroll 1
    for (int kt = 0; kt < KT; ++kt) {
        if (kt + 1 < KT) cp_wait<1>(); else cp_wait<0>();
        __syncthreads();
        if (kt + 2 < KT) K3_ISSUE(kt + 2, (kt + 2) % 3);

        const int sA_ = (kt % 3) * ASTG;
        const int sB_ = ABASE + (kt % 3) * NB3;
#pragma unroll
        for (int kc = 0; kc < 2; ++kc) {
            uint32_t a0, a1, a2, a3;
            ldsm4(a0, a1, a2, a3, aBase + 4 * sA_ + kc * 32);
            const int bb = sB_ + 8 * kc * BROW + bfr;
            uint4 b0 = *(const uint4*)&smem[bb];
            uint4 b1 = *(const uint4*)&smem[bb + 4 * BROW];
            mma_f16(acc[0], a0, a1, a2, a3, b0.x, b1.x);
            mma_f16(acc[1], a0, a1, a2, a3, b0.y, b1.y);
            mma_f16(acc[2], a0, a1, a2, a3, b0.z, b1.z);
            mma_f16(acc[3], a0, a1, a2, a3, b0.w, b1.w);
        }
    }
#undef K3_ISSUE

    float dotr[2] = {0.0f, 0.0f};
#pragma unroll
    for (int ri = 0; ri < 2; ri++) {
#pragma unroll
        for (int nt = 0; nt < 4; nt++) {
#pragma unroll
            for (int cj = 0; cj < 2; cj++) {
                int c = col0 + nt * 8 + 2 * klo + cj;
                int idx = ri * 2 + cj;
                float rv = fmaxf(acc[nt][idx] + b_r1[c], 0.0f);
                dotr[ri] = fmaf(rv, w_r2[c], dotr[ri]);
            }
        }
    }
#pragma unroll
    for (int ri = 0; ri < 2; ri++) {
        float D = red4(dotr[ri]);
        if (klo == 0) {
            int b = row0 + r1 + ri * 8;
            g_rD[(size_t)(t * 16 + by) * BDIM + b] = D;
        }
    }
}

// ---------------------------------------------------------------------------
// k_efe: fold all per-step partials into g_acc (once). grid 16 x 256.
// ---------------------------------------------------------------------------
__global__ void k_efe() {
    const int b = blockIdx.x * 256 + threadIdx.x;
    float acc = 0.0f, disc = 1.0f;
#pragma unroll 1
    for (int t = 0; t < TSTEPS; t++) {
        float S = 0.0f, Q = 0.0f, D = 0.0f;
#pragma unroll
        for (int i = 0; i < 32; i++) {
            S += g_hS[(size_t)(t * 32 + i) * BDIM + b];
            Q += g_hQ[(size_t)(t * 32 + i) * BDIM + b];
        }
#pragma unroll
        for (int i = 0; i < 8; i++) {
            S += g_sS[(size_t)(t * 8 + i) * BDIM + b];
            Q += g_sQ[(size_t)(t * 8 + i) * BDIM + b];
        }
#pragma unroll
        for (int i = 0; i < 16; i++) D += g_rD[(size_t)(t * 16 + i) * BDIM + b];
        float mean = S * (1.0f / 1280.0f);
        float var = Q * (1.0f / 1280.0f) - mean * mean;
        acc += disc * (D + var);
        disc *= 0.99f;
    }
    g_acc[b] = acc;
}

__global__ void k_final(float* __restrict__ out, const float* __restrict__ b_r2,
                        float discsum) {
    const int a = blockIdx.x;
    const int tid = threadIdx.x;
    float v = g_acc[a * NSAMP + tid];
#pragma unroll
    for (int off = 16; off > 0; off >>= 1) v += __shfl_down_sync(0xffffffffu, v, off);
    __shared__ float w[8];
    if ((tid & 31) == 0) w[tid >> 5] = v;
    __syncthreads();
    if (tid < 8) {
        float x = w[tid];
#pragma unroll
        for (int off = 4; off > 0; off >>= 1) x += __shfl_down_sync(0xffu, x, off);
        if (tid == 0) out[a] = -(x * (1.0f / (float)NSAMP) + discsum * b_r2[0]);
    }
}

// ---------------------------------------------------------------------------
extern "C" void kernel_launch(void* const* d_in, const int* in_sizes, int n_in,
                              void* d_out, int out_size) {
    (void)in_sizes; (void)n_in; (void)out_size;
    const float* h0    = (const float*)d_in[0];
    const float* s0    = (const float*)d_in[1];
    const float* noise = (const float*)d_in[2];
    const float* Wx    = (const float*)d_in[3];
    const float* Wh    = (const float*)d_in[4];
    const float* b_gru = (const float*)d_in[5];
    const float* W_mu  = (const float*)d_in[6];
    const float* b_mu  = (const float*)d_in[7];
    const float* W_std = (const float*)d_in[8];
    const float* b_std = (const float*)d_in[9];
    const float* W_r1  = (const float*)d_in[10];
    const float* b_r1  = (const float*)d_in[11];
    const float* w_r2  = (const float*)d_in[12];
    const float* b_r2  = (const float*)d_in[13];
    const int*   acts  = (const int*)d_in[14];
    float* out = (float*)d_out;

    const int SM1 = (ABASE + 3 * NB1) * 4;   // 53760 B
    const int SM2 = (ABASE + 3 * NB2) * 4;   // 46080 B
    const int SM3 = (ABASE + 3 * NB3) * 4;   // 38400 B
    cudaFuncSetAttribute(k1_gru, cudaFuncAttributeMaxDynamicSharedMemorySize, SM1);
    cudaFuncSetAttribute(k2_latent, cudaFuncAttributeMaxDynamicSharedMemorySize, SM2);
    cudaFuncSetAttribute(k3_reward, cudaFuncAttributeMaxDynamicSharedMemorySize, SM3);

    k_init<<<512, 256>>>(h0, s0);
    k_prep1<<<2048, 256>>>(Wx, Wh);
    k_prep2<<<256, 256>>>(W_mu, W_std);
    k_prep3<<<320, 256>>>(W_r1);

    for (int t = 0; t < TSTEPS; ++t) {
        int par = t & 1;
        int parn = par ^ 1;
        k1_gru<<<dim3(BDIM / BM, HDIM / BN), 256, SM1>>>(par, t, Wx, b_gru,
                                                         acts + (size_t)t * BDIM);
        k2_latent<<<dim3(BDIM / BM, SDIM / BN), 256, SM2>>>(parn, t, b_mu, b_std,
                                                            noise + (size_t)t * BDIM * SDIM);
        k3_reward<<<dim3(BDIM / BM, RHDIM / BN), 256, SM3>>>(parn, t, b_r1, w_r2);
    }
    k_efe<<<16, 256>>>();

    float discsum = 0.0f, d = 1.0f;
    for (int t = 0; t < TSTEPS; ++t) { discsum += d; d *= 0.99f; }
    k_final<<<16, 256>>>(out, b_r2, discsum);
}

// round 9
// speedup vs baseline: 1.6336x; 1.0225x over previous
#include <cuda_runtime.h>
#include <cuda_fp16.h>
#include <math.h>
#include <cstdint>

// Problem constants
#define BDIM 4096
#define HDIM 1024
#define SDIM 256
#define NSAMP 256
#define TSTEPS 10
#define RHDIM 512
#define N3 3072

// Tiling: BM=128, BN=32, BK=32 (halves), 8 warps x (16 rows x 32 cols)
#define BM 128
#define BN 32
#define AROW 20              // A smem row stride in words (32 halves + pad 8)
#define ASTG 2560            // A words per stage (128*20)
#define ABASE 7680           // 3 * ASTG
#define BROW 40              // B smem k2-row stride in words
#define NB1 1920
#define NB2 1280
#define NB3 640

// Persistent scratch
__device__ float g_h[2][BDIM * HDIM];
__device__ __half g_h16[2][BDIM * HDIM];
__device__ __half g_s16[BDIM * SDIM];
__device__ float g_acc[BDIM];
// per-step per-CTA-column partial sums (deterministic, no atomics)
__device__ float g_hS[TSTEPS * 32 * BDIM];
__device__ float g_hQ[TSTEPS * 32 * BDIM];
__device__ float g_sS[TSTEPS * 8 * BDIM];
__device__ float g_sQ[TSTEPS * 8 * BDIM];
__device__ float g_rD[TSTEPS * 16 * BDIM];
// Pre-packed half2 weights
__device__ uint32_t W1h[32 * 40 * 3 * 16 * 32];
__device__ uint32_t W2h[8 * 32 * 2 * 16 * 32];
__device__ uint32_t W3h[16 * 40 * 16 * 32];

__device__ __forceinline__ float sigm_(float x) { return 1.0f / (1.0f + expf(-x)); }
__device__ __forceinline__ float softplus_(float x) {
    return fmaxf(x, 0.0f) + log1pf(expf(-fabsf(x)));
}
__device__ __forceinline__ uint32_t pack2(float lo, float hi) {
    __half2 h = __floats2half2_rn(lo, hi);
    return *(uint32_t*)&h;
}
__device__ __forceinline__ float red4(float v) {
    v += __shfl_xor_sync(0xffffffffu, v, 1);
    v += __shfl_xor_sync(0xffffffffu, v, 2);
    return v;
}
__device__ __forceinline__ void mma_f16(float c[4], uint32_t a0, uint32_t a1,
                                        uint32_t a2, uint32_t a3,
                                        uint32_t b0, uint32_t b1) {
    asm volatile(
        "mma.sync.aligned.m16n8k16.row.col.f32.f16.f16.f32 "
        "{%0,%1,%2,%3},{%4,%5,%6,%7},{%8,%9},{%0,%1,%2,%3};\n"
        : "+f"(c[0]), "+f"(c[1]), "+f"(c[2]), "+f"(c[3])
        : "r"(a0), "r"(a1), "r"(a2), "r"(a3), "r"(b0), "r"(b1));
}
__device__ __forceinline__ void ldsm4(uint32_t& r0, uint32_t& r1, uint32_t& r2,
                                      uint32_t& r3, uint32_t addr) {
    asm volatile("ldmatrix.sync.aligned.m8n8.x4.shared.b16 {%0,%1,%2,%3}, [%4];"
                 : "=r"(r0), "=r"(r1), "=r"(r2), "=r"(r3) : "r"(addr));
}
__device__ __forceinline__ void cp16(uint32_t dst, const void* src) {
    asm volatile("cp.async.cg.shared.global [%0], [%1], 16;" :: "r"(dst), "l"(src));
}
__device__ __forceinline__ void cp_commit() { asm volatile("cp.async.commit_group;"); }
template<int N> __device__ __forceinline__ void cp_wait() {
    asm volatile("cp.async.wait_group %0;" :: "n"(N));
}

// ---------------------------------------------------------------------------
// init + weight packing
// ---------------------------------------------------------------------------
__global__ void k_init(const float* __restrict__ h0, const float* __restrict__ s0) {
    int idx = blockIdx.x * blockDim.x + threadIdx.x;
    int stride = gridDim.x * blockDim.x;
    for (int i = idx; i < BDIM * HDIM; i += stride) {
        float v = h0[i & (HDIM - 1)];
        g_h[0][i] = v; g_h16[0][i] = __float2half_rn(v);
    }
    for (int i = idx; i < BDIM * SDIM; i += stride)
        g_s16[i] = __float2half_rn(s0[i & (SDIM - 1)]);
}

__global__ void k_prep1(const float* __restrict__ Wx, const float* __restrict__ Wh) {
    const int total = 32 * 40 * 3 * 16 * 32;
    for (int idx = blockIdx.x * blockDim.x + threadIdx.x; idx < total;
         idx += gridDim.x * blockDim.x) {
        int p = idx & 31, k2 = (idx >> 5) & 15;
        int rest = idx >> 9;
        int g = rest % 3; rest /= 3;
        int kt = rest % 40; int cb = rest / 40;
        int c = (p & 3) * 8 + (p >> 2);
        int col = g * HDIM + cb * 32 + c;
        int row = kt * 32 + 2 * k2;
        float vlo, vhi;
        if (row < 256) { vlo = Wx[(size_t)row * N3 + col]; vhi = Wx[(size_t)(row + 1) * N3 + col]; }
        else { vlo = Wh[(size_t)(row - 256) * N3 + col]; vhi = Wh[(size_t)(row - 255) * N3 + col]; }
        W1h[idx] = pack2(vlo, vhi);
    }
}
__global__ void k_prep2(const float* __restrict__ W_mu, const float* __restrict__ W_std) {
    const int total = 8 * 32 * 2 * 16 * 32;
    for (int idx = blockIdx.x * blockDim.x + threadIdx.x; idx < total;
         idx += gridDim.x * blockDim.x) {
        int p = idx & 31, k2 = (idx >> 5) & 15;
        int rest = idx >> 9;
        int g = rest & 1; rest >>= 1;
        int kt = rest & 31; int cb = rest >> 5;
        int c = (p & 3) * 8 + (p >> 2);
        const float* W = g ? W_std : W_mu;
        int row = kt * 32 + 2 * k2;
        W2h[idx] = pack2(W[(size_t)row * SDIM + cb * 32 + c],
                         W[(size_t)(row + 1) * SDIM + cb * 32 + c]);
    }
}
__global__ void k_prep3(const float* __restrict__ W_r1) {
    const int total = 16 * 40 * 16 * 32;
    for (int idx = blockIdx.x * blockDim.x + threadIdx.x; idx < total;
         idx += gridDim.x * blockDim.x) {
        int p = idx & 31, k2 = (idx >> 5) & 15;
        int rest = idx >> 9;
        int kt = rest % 40; int cb = rest / 40;
        int c = (p & 3) * 8 + (p >> 2);
        int row = kt * 32 + 2 * k2;
        W3h[idx] = pack2(W_r1[(size_t)row * RHDIM + cb * 32 + c],
                         W_r1[(size_t)(row + 1) * RHDIM + cb * 32 + c]);
    }
}

// ---------------------------------------------------------------------------
// K1 tile body: GRU gates GEMM + h update + h partial sums. col-block = by.
// ---------------------------------------------------------------------------
__device__ __forceinline__
void k1_body(int par, int t, const float* __restrict__ Wx,
             const float* __restrict__ b_gru, const int* __restrict__ acts_t, int by) {
    extern __shared__ uint32_t smem[];
    const float* __restrict__ h_in = g_h[par];
    float* __restrict__ h_out = g_h[par ^ 1];
    const __half* __restrict__ h16_in = g_h16[par];
    __half* __restrict__ h16_out = g_h16[par ^ 1];

    const int tid = threadIdx.x, lane = tid & 31, warp = tid >> 5;
    const int row0 = blockIdx.x * BM, col0 = by * BN;
    const int wr = warp * 16;
    const uint32_t smem_b = (uint32_t)__cvta_generic_to_shared(smem);

    const int c4 = tid & 3, rA = tid >> 2;
    const int wA0 = rA * AROW + c4 * 4, wA1 = (rA + 64) * AROW + c4 * 4;
    const __half* sA = g_s16 + (size_t)(row0 + rA) * SDIM + c4 * 8;
    const __half* hA = h16_in + (size_t)(row0 + rA) * HDIM + c4 * 8;
    const int bg0 = tid >> 7, bk0 = (tid >> 3) & 15, bc0 = tid & 7;
    const int wB0 = bg0 * 640 + bk0 * BROW + bc0 * 4;
    const int sB0w = bg0 * 512 + bk0 * 32 + bc0 * 4;
    const int wB1 = 2 * 640 + (tid >> 3) * BROW + (tid & 7) * 4;
    const int sB1w = 2 * 512 + (tid >> 3) * 32 + (tid & 7) * 4;
    const uint32_t* wblk = W1h + (size_t)by * (40 * 3 * 512);

#define K1_ISSUE(kt, s) do {                                                  \
    const __half* ap; int astr;                                               \
    if ((kt) < 8) { ap = sA + (kt) * 32; astr = SDIM; }                       \
    else { ap = hA + ((kt) - 8) * 32; astr = HDIM; }                          \
    cp16(smem_b + 4 * ((s) * ASTG + wA0), ap);                                \
    cp16(smem_b + 4 * ((s) * ASTG + wA1), ap + 64 * astr);                    \
    const uint32_t* wp = wblk + (size_t)(kt) * 1536;                          \
    cp16(smem_b + 4 * (ABASE + (s) * NB1 + wB0), wp + sB0w);                  \
    if (tid < 128) cp16(smem_b + 4 * (ABASE + (s) * NB1 + wB1), wp + sB1w);   \
    cp_commit(); } while (0)

    float acc[3][4][4], accNX[4][4];
#pragma unroll
    for (int g = 0; g < 3; g++)
#pragma unroll
        for (int nt = 0; nt < 4; nt++)
#pragma unroll
            for (int r = 0; r < 4; r++) acc[g][nt][r] = 0.0f;

    const int q = lane >> 2, klo = lane & 3;
    const int r1 = wr + q;
    const int bfr = klo * BROW + q * 4;
    const uint32_t aBase = smem_b + (uint32_t)(wr + (lane & 15)) * AROW * 4
                         + ((lane >> 4) * 16);

    K1_ISSUE(0, 0);
    K1_ISSUE(1, 1);

    const int KT = 40;
#pragma unroll 1
    for (int kt = 0; kt < KT; ++kt) {
        if (kt + 1 < KT) cp_wait<1>(); else cp_wait<0>();
        __syncthreads();
        if (kt + 2 < KT) K1_ISSUE(kt + 2, (kt + 2) % 3);

        if (kt == 8) {
#pragma unroll
            for (int nt = 0; nt < 4; nt++)
#pragma unroll
                for (int r = 0; r < 4; r++) { accNX[nt][r] = acc[2][nt][r]; acc[2][nt][r] = 0.0f; }
        }
        const int sA_ = (kt % 3) * ASTG;
        const int sB_ = ABASE + (kt % 3) * NB1;
#pragma unroll
        for (int kc = 0; kc < 2; ++kc) {
            uint32_t a0, a1, a2, a3;
            ldsm4(a0, a1, a2, a3, aBase + 4 * sA_ + kc * 32);
#pragma unroll
            for (int g = 0; g < 3; g++) {
                const int bb = sB_ + g * 640 + 8 * kc * BROW + bfr;
                uint4 b0 = *(const uint4*)&smem[bb];
                uint4 b1 = *(const uint4*)&smem[bb + 4 * BROW];
                mma_f16(acc[g][0], a0, a1, a2, a3, b0.x, b1.x);
                mma_f16(acc[g][1], a0, a1, a2, a3, b0.y, b1.y);
                mma_f16(acc[g][2], a0, a1, a2, a3, b0.z, b1.z);
                mma_f16(acc[g][3], a0, a1, a2, a3, b0.w, b1.w);
            }
        }
    }
#undef K1_ISSUE

    float sumr[2] = {0.0f, 0.0f}, sqr[2] = {0.0f, 0.0f};
#pragma unroll
    for (int ri = 0; ri < 2; ri++) {
        int b = row0 + r1 + ri * 8;
        int a = acts_t[b];
        const float* wa = Wx + (size_t)(SDIM + a) * N3;
#pragma unroll
        for (int nt = 0; nt < 4; nt++) {
#pragma unroll
            for (int cj = 0; cj < 2; cj++) {
                int c = col0 + nt * 8 + 2 * klo + cj;
                int idx = ri * 2 + cj;
                float z = sigm_(acc[0][nt][idx] + wa[c] + b_gru[c]);
                float r = sigm_(acc[1][nt][idx] + wa[HDIM + c] + b_gru[HDIM + c]);
                float n = tanhf(accNX[nt][idx] + wa[2 * HDIM + c]
                                + r * acc[2][nt][idx] + b_gru[2 * HDIM + c]);
                float hp = h_in[(size_t)b * HDIM + c];
                float hv = (1.0f - z) * hp + z * n;
                h_out[(size_t)b * HDIM + c] = hv;
                h16_out[(size_t)b * HDIM + c] = __float2half_rn(hv);
                sumr[ri] += hv;
                sqr[ri] = fmaf(hv, hv, sqr[ri]);
            }
        }
    }
#pragma unroll
    for (int ri = 0; ri < 2; ri++) {
        float S = red4(sumr[ri]);
        float Q = red4(sqr[ri]);
        if (klo == 0) {
            int b = row0 + r1 + ri * 8;
            g_hS[(size_t)(t * 32 + by) * BDIM + b] = S;
            g_hQ[(size_t)(t * 32 + by) * BDIM + b] = Q;
        }
    }
}

// ---------------------------------------------------------------------------
// K3 tile body: reward hidden GEMM + fused relu.w_r2 partial dot. col-block by.
// ---------------------------------------------------------------------------
__device__ __forceinline__
void k3_body(int parn, int t, const float* __restrict__ b_r1,
             const float* __restrict__ w_r2, int by) {
    extern __shared__ uint32_t smem[];
    const __half* __restrict__ h16 = g_h16[parn];

    const int tid = threadIdx.x, lane = tid & 31, warp = tid >> 5;
    const int row0 = blockIdx.x * BM, col0 = by * BN;
    const int wr = warp * 16;
    const uint32_t smem_b = (uint32_t)__cvta_generic_to_shared(smem);

    const int c4 = tid & 3, rA = tid >> 2;
    const int wA0 = rA * AROW + c4 * 4, wA1 = (rA + 64) * AROW + c4 * 4;
    const __half* hA = h16 + (size_t)(row0 + rA) * HDIM + c4 * 8;
    const __half* sA = g_s16 + (size_t)(row0 + rA) * SDIM + c4 * 8;
    const int wB0 = (tid >> 3) * BROW + (tid & 7) * 4;
    const int sB0w = (tid >> 3) * 32 + (tid & 7) * 4;
    const uint32_t* wblk = W3h + (size_t)by * (40 * 512);

#define K3_ISSUE(kt, s) do {                                                  \
    const __half* ap; int astr;                                               \
    if ((kt) < 32) { ap = hA + (kt) * 32; astr = HDIM; }                      \
    else { ap = sA + ((kt) - 32) * 32; astr = SDIM; }                         \
    cp16(smem_b + 4 * ((s) * ASTG + wA0), ap);                                \
    cp16(smem_b + 4 * ((s) * ASTG + wA1), ap + 64 * astr);                    \
    if (tid < 128)                                                            \
        cp16(smem_b + 4 * (ABASE + (s) * NB3 + wB0), wblk + (size_t)(kt) * 512 + sB0w); \
    cp_commit(); } while (0)

    float acc[4][4];
#pragma unroll
    for (int nt = 0; nt < 4; nt++)
#pragma unroll
        for (int r = 0; r < 4; r++) acc[nt][r] = 0.0f;

    const int q = lane >> 2, klo = lane & 3;
    const int r1 = wr + q;
    const int bfr = klo * BROW + q * 4;
    const uint32_t aBase = smem_b + (uint32_t)(wr + (lane & 15)) * AROW * 4
                         + ((lane >> 4) * 16);

    K3_ISSUE(0, 0);
    K3_ISSUE(1, 1);

    const int KT = 40;
#pragma unroll 1
    for (int kt = 0; kt < KT; ++kt) {
        if (kt + 1 < KT) cp_wait<1>(); else cp_wait<0>();
        __syncthreads();
        if (kt + 2 < KT) K3_ISSUE(kt + 2, (kt + 2) % 3);

        const int sA_ = (kt % 3) * ASTG;
        const int sB_ = ABASE + (kt % 3) * NB3;
#pragma unroll
        for (int kc = 0; kc < 2; ++kc) {
            uint32_t a0, a1, a2, a3;
            ldsm4(a0, a1, a2, a3, aBase + 4 * sA_ + kc * 32);
            const int bb = sB_ + 8 * kc * BROW + bfr;
            uint4 b0 = *(const uint4*)&smem[bb];
            uint4 b1 = *(const uint4*)&smem[bb + 4 * BROW];
            mma_f16(acc[0], a0, a1, a2, a3, b0.x, b1.x);
            mma_f16(acc[1], a0, a1, a2, a3, b0.y, b1.y);
            mma_f16(acc[2], a0, a1, a2, a3, b0.z, b1.z);
            mma_f16(acc[3], a0, a1, a2, a3, b0.w, b1.w);
        }
    }
#undef K3_ISSUE

    float dotr[2] = {0.0f, 0.0f};
#pragma unroll
    for (int ri = 0; ri < 2; ri++) {
#pragma unroll
        for (int nt = 0; nt < 4; nt++) {
#pragma unroll
            for (int cj = 0; cj < 2; cj++) {
                int c = col0 + nt * 8 + 2 * klo + cj;
                int idx = ri * 2 + cj;
                float rv = fmaxf(acc[nt][idx] + b_r1[c], 0.0f);
                dotr[ri] = fmaf(rv, w_r2[c], dotr[ri]);
            }
        }
    }
#pragma unroll
    for (int ri = 0; ri < 2; ri++) {
        float D = red4(dotr[ri]);
        if (klo == 0) {
            int b = row0 + r1 + ri * 8;
            g_rD[(size_t)(t * 16 + by) * BDIM + b] = D;
        }
    }
}

// ---------------------------------------------------------------------------
// Merged k1(t) + k3(t-1): identical inputs (h16[par], s16), disjoint outputs.
// grid (32, 48) for t>=1; (32, 32) for t=0.
// ---------------------------------------------------------------------------
__global__ __launch_bounds__(256, 2)
void k13(int par, int t, const float* __restrict__ Wx, const float* __restrict__ b_gru,
         const int* __restrict__ acts_t, const float* __restrict__ b_r1,
         const float* __restrict__ w_r2) {
    if (blockIdx.y < 32) k1_body(par, t, Wx, b_gru, acts_t, blockIdx.y);
    else k3_body(par, t - 1, b_r1, w_r2, blockIdx.y - 32);
}

__global__ __launch_bounds__(256, 2)
void k3k(int parn, int t, const float* __restrict__ b_r1, const float* __restrict__ w_r2) {
    k3_body(parn, t, b_r1, w_r2, blockIdx.y);
}

// ---------------------------------------------------------------------------
// K2: mu/std GEMM + latent sample + s partial sums. grid (32,8).
// ---------------------------------------------------------------------------
__global__ __launch_bounds__(256, 2)
void k2_latent(int parn, int t, const float* __restrict__ b_mu,
               const float* __restrict__ b_std, const float* __restrict__ noise_t) {
    extern __shared__ uint32_t smem[];
    const __half* __restrict__ h16 = g_h16[parn];

    const int tid = threadIdx.x, lane = tid & 31, warp = tid >> 5;
    const int row0 = blockIdx.x * BM, col0 = blockIdx.y * BN, by = blockIdx.y;
    const int wr = warp * 16;
    const uint32_t smem_b = (uint32_t)__cvta_generic_to_shared(smem);

    const int c4 = tid & 3, rA = tid >> 2;
    const int wA0 = rA * AROW + c4 * 4, wA1 = (rA + 64) * AROW + c4 * 4;
    const __half* hA = h16 + (size_t)(row0 + rA) * HDIM + c4 * 8;
    const int bg0 = tid >> 7, bk0 = (tid >> 3) & 15, bc0 = tid & 7;
    const int wB0 = bg0 * 640 + bk0 * BROW + bc0 * 4;
    const int sB0w = bg0 * 512 + bk0 * 32 + bc0 * 4;
    const uint32_t* wblk = W2h + (size_t)blockIdx.y * (32 * 2 * 512);

#define K2_ISSUE(kt, s) do {                                                  \
    const __half* ap = hA + (kt) * 32;                                        \
    cp16(smem_b + 4 * ((s) * ASTG + wA0), ap);                                \
    cp16(smem_b + 4 * ((s) * ASTG + wA1), ap + 64 * HDIM);                    \
    const uint32_t* wp = wblk + (size_t)(kt) * 1024;                          \
    cp16(smem_b + 4 * (ABASE + (s) * NB2 + wB0), wp + sB0w);                  \
    cp_commit(); } while (0)

    float acc[2][4][4];
#pragma unroll
    for (int g = 0; g < 2; g++)
#pragma unroll
        for (int nt = 0; nt < 4; nt++)
#pragma unroll
            for (int r = 0; r < 4; r++) acc[g][nt][r] = 0.0f;

    const int q = lane >> 2, klo = lane & 3;
    const int r1 = wr + q;
    const int bfr = klo * BROW + q * 4;
    const uint32_t aBase = smem_b + (uint32_t)(wr + (lane & 15)) * AROW * 4
                         + ((lane >> 4) * 16);

    K2_ISSUE(0, 0);
    K2_ISSUE(1, 1);

    const int KT = 32;
#pragma unroll 1
    for (int kt = 0; kt < KT; ++kt) {
        if (kt + 1 < KT) cp_wait<1>(); else cp_wait<0>();
        __syncthreads();
        if (kt + 2 < KT) K2_ISSUE(kt + 2, (kt + 2) % 3);

        const int sA_ = (kt % 3) * ASTG;
        const int sB_ = ABASE + (kt % 3) * NB2;
#pragma unroll
        for (int kc = 0; kc < 2; ++kc) {
            uint32_t a0, a1, a2, a3;
            ldsm4(a0, a1, a2, a3, aBase + 4 * sA_ + kc * 32);
#pragma unroll
            for (int g = 0; g < 2; g++) {
                const int bb = sB_ + g * 640 + 8 * kc * BROW + bfr;
                uint4 b0 = *(const uint4*)&smem[bb];
                uint4 b1 = *(const uint4*)&smem[bb + 4 * BROW];
                mma_f16(acc[g][0], a0, a1, a2, a3, b0.x, b1.x);
                mma_f16(acc[g][1], a0, a1, a2, a3, b0.y, b1.y);
                mma_f16(acc[g][2], a0, a1, a2, a3, b0.z, b1.z);
                mma_f16(acc[g][3], a0, a1, a2, a3, b0.w, b1.w);
            }
        }
    }
#undef K2_ISSUE

    float sumr[2] = {0.0f, 0.0f}, sqr[2] = {0.0f, 0.0f};
#pragma unroll
    for (int ri = 0; ri < 2; ri++) {
        int b = row0 + r1 + ri * 8;
#pragma unroll
        for (int nt = 0; nt < 4; nt++) {
#pragma unroll
            for (int cj = 0; cj < 2; cj++) {
                int c = col0 + nt * 8 + 2 * klo + cj;
                int idx = ri * 2 + cj;
                float mu = acc[0][nt][idx] + b_mu[c];
                float sd = softplus_(acc[1][nt][idx] + b_std[c]) + 0.1f;
                float sv = mu + sd * noise_t[(size_t)b * SDIM + c];
                g_s16[(size_t)b * SDIM + c] = __float2half_rn(sv);
                sumr[ri] += sv;
                sqr[ri] = fmaf(sv, sv, sqr[ri]);
            }
        }
    }
#pragma unroll
    for (int ri = 0; ri < 2; ri++) {
        float S = red4(sumr[ri]);
        float Q = red4(sqr[ri]);
        if (klo == 0) {
            int b = row0 + r1 + ri * 8;
            g_sS[(size_t)(t * 8 + by) * BDIM + b] = S;
            g_sQ[(size_t)(t * 8 + by) * BDIM + b] = Q;
        }
    }
}

// ---------------------------------------------------------------------------
// k_efe: fold all per-step partials into g_acc (once). grid 16 x 256.
// ---------------------------------------------------------------------------
__global__ void k_efe() {
    const int b = blockIdx.x * 256 + threadIdx.x;
    float acc = 0.0f, disc = 1.0f;
#pragma unroll 1
    for (int t = 0; t < TSTEPS; t++) {
        float S = 0.0f, Q = 0.0f, D = 0.0f;
#pragma unroll
        for (int i = 0; i < 32; i++) {
            S += g_hS[(size_t)(t * 32 + i) * BDIM + b];
            Q += g_hQ[(size_t)(t * 32 + i) * BDIM + b];
        }
#pragma unroll
        for (int i = 0; i < 8; i++) {
            S += g_sS[(size_t)(t * 8 + i) * BDIM + b];
            Q += g_sQ[(size_t)(t * 8 + i) * BDIM + b];
        }
#pragma unroll
        for (int i = 0; i < 16; i++) D += g_rD[(size_t)(t * 16 + i) * BDIM + b];
        float mean = S * (1.0f / 1280.0f);
        float var = Q * (1.0f / 1280.0f) - mean * mean;
        acc += disc * (D + var);
        disc *= 0.99f;
    }
    g_acc[b] = acc;
}

__global__ void k_final(float* __restrict__ out, const float* __restrict__ b_r2,
                        float discsum) {
    const int a = blockIdx.x;
    const int tid = threadIdx.x;
    float v = g_acc[a * NSAMP + tid];
#pragma unroll
    for (int off = 16; off > 0; off >>= 1) v += __shfl_down_sync(0xffffffffu, v, off);
    __shared__ float w[8];
    if ((tid & 31) == 0) w[tid >> 5] = v;
    __syncthreads();
    if (tid < 8) {
        float x = w[tid];
#pragma unroll
        for (int off = 4; off > 0; off >>= 1) x += __shfl_down_sync(0xffu, x, off);
        if (tid == 0) out[a] = -(x * (1.0f / (float)NSAMP) + discsum * b_r2[0]);
    }
}

// ---------------------------------------------------------------------------
extern "C" void kernel_launch(void* const* d_in, const int* in_sizes, int n_in,
                              void* d_out, int out_size) {
    (void)in_sizes; (void)n_in; (void)out_size;
    const float* h0    = (const float*)d_in[0];
    const float* s0    = (const float*)d_in[1];
    const float* noise = (const float*)d_in[2];
    const float* Wx    = (const float*)d_in[3];
    const float* Wh    = (const float*)d_in[4];
    const float* b_gru = (const float*)d_in[5];
    const float* W_mu  = (const float*)d_in[6];
    const float* b_mu  = (const float*)d_in[7];
    const float* W_std = (const float*)d_in[8];
    const float* b_std = (const float*)d_in[9];
    const float* W_r1  = (const float*)d_in[10];
    const float* b_r1  = (const float*)d_in[11];
    const float* w_r2  = (const float*)d_in[12];
    const float* b_r2  = (const float*)d_in[13];
    const int*   acts  = (const int*)d_in[14];
    float* out = (float*)d_out;

    const int SM1 = (ABASE + 3 * NB1) * 4;   // 53760 B
    const int SM2 = (ABASE + 3 * NB2) * 4;   // 46080 B
    cudaFuncSetAttribute(k13, cudaFuncAttributeMaxDynamicSharedMemorySize, SM1);
    cudaFuncSetAttribute(k3k, cudaFuncAttributeMaxDynamicSharedMemorySize, SM1);
    cudaFuncSetAttribute(k2_latent, cudaFuncAttributeMaxDynamicSharedMemorySize, SM2);

    k_init<<<512, 256>>>(h0, s0);
    k_prep1<<<2048, 256>>>(Wx, Wh);
    k_prep2<<<256, 256>>>(W_mu, W_std);
    k_prep3<<<320, 256>>>(W_r1);

    for (int t = 0; t < TSTEPS; ++t) {
        int par = t & 1;
        int parn = par ^ 1;
        int ny = (t == 0) ? 32 : 48;
        k13<<<dim3(BDIM / BM, ny), 256, SM1>>>(par, t, Wx, b_gru,
                                               acts + (size_t)t * BDIM, b_r1, w_r2);
        k2_latent<<<dim3(BDIM / BM, SDIM / BN), 256, SM2>>>(parn, t, b_mu, b_std,
                                                            noise + (size_t)t * BDIM * SDIM);
    }
    // final step's reward GEMM (state after t=9: parn = (9&1)^1 = 0)
    k3k<<<dim3(BDIM / BM, RHDIM / BN), 256, SM1>>>(0, TSTEPS - 1, b_r1, w_r2);
    k_efe<<<16, 256>>>();

    float discsum = 0.0f, d = 1.0f;
    for (int t = 0; t < TSTEPS; ++t) { discsum += d; d *= 0.99f; }
    k_final<<<16, 256>>>(out, b_r2, discsum);
}